// round 15
// baseline (speedup 1.0000x reference)
#include <cuda_runtime.h>
#include <cuda_bf16.h>
#include <stdint.h>
#include <math.h>

#define NTOK 8192
#define KCB  8192
#define NEGB (-1e9f)

typedef __nv_bfloat16 bf16;
typedef __nv_bfloat162 bf162;
typedef const float* cfp;

// plane strides
#define NA  (8192LL*768)
#define NF  (8192LL*2048)
#define NQ  (8192LL*2304)
#define NVT (8388608LL)           // vT plane: 128*128*512

// pre-split weight wall: offsets (elems) and total
#define W_SIW 0LL
#define W_SOW 10616832LL
#define W_CIW 14155776LL
#define W_COW 24772608LL
#define W_W1  28311552LL
#define W_W2  37748736LL
#define W_OW  47185920LL
#define NW    47775744LL

// smem tile: 128 rows x 56 elems (112B stride, conflict-free for ldmatrix)
#define TROW 56
#define TILEB (128*TROW*2)        // 14336 bytes
#define PVSMEM (8*TILEB + 512)

// ------------- static device scratch -------------
static __device__ float g_ze[NTOK*768];
static __device__ float g_h[NTOK*768];
static __device__ float g_proj[NTOK*768];
static __device__ float g_scores[128*512*512];
static __device__ float g_cn[KCB];
static __device__ float g_zsq[NTOK];
static __device__ float g_padbias[NTOK];
static __device__ float g_topd[NTOK*10];
static __device__ int   g_topi[NTOK*10];
static __device__ int   g_enc[NTOK];
static __device__ int   g_ci[NTOK*16];
// bf16 buffers
static __device__ __align__(16) bf16 g_dotb[(long long)NTOK*KCB];   // coarse dots, single plane
static __device__ __align__(16) bf16 g_zsp[2*NA];
static __device__ __align__(16) bf16 g_hsp[2*NA];
static __device__ __align__(16) bf16 g_atsp[2*NA];
static __device__ __align__(16) bf16 g_fsp[2*NF];
static __device__ __align__(16) bf16 g_qsp[2*NQ];
static __device__ __align__(16) bf16 g_cbsp[2*NA];
static __device__ __align__(16) bf16 g_vtsp[2*NVT];                 // rows n>=96 stay zero
static __device__ __align__(16) bf16 g_wall[2*NW];

// ------------- helpers -------------
__device__ __forceinline__ float blkSum(float v, float* red) {
    #pragma unroll
    for (int o = 16; o; o >>= 1) v += __shfl_xor_sync(0xffffffffu, v, o);
    if ((threadIdx.x & 31) == 0) red[threadIdx.x >> 5] = v;
    __syncthreads();
    float s = red[0];
    #pragma unroll
    for (int i = 1; i < 8; ++i) s += red[i];
    __syncthreads();
    return s;
}
__device__ __forceinline__ uint32_t s2u(const void* p) {
    uint32_t a;
    asm("{ .reg .u64 t; cvta.to.shared.u64 t, %1; cvt.u32.u64 %0, t; }" : "=r"(a) : "l"(p));
    return a;
}
__device__ __forceinline__ void splitWr(bf16* Cb, long long Cs, long long off, float a, float b) {
    bf16 h0 = __float2bfloat16(a), h1 = __float2bfloat16(b);
    bf162 p0; p0.x = h0; p0.y = h1;
    bf162 p1; p1.x = __float2bfloat16(a - __bfloat162float(h0));
    p1.y = __float2bfloat16(b - __bfloat162float(h1));
    *(bf162*)&Cb[off] = p0;
    *(bf162*)&Cb[Cs + off] = p1;
}

// ------------- z_e, pad, |z|^2 (+fused split) -------------
__global__ __launch_bounds__(256) void ze_kernel(const float* __restrict__ x) {
    int n = blockIdx.x;
    __shared__ float red[8];
    float v[3]; float ss = 0.f;
    #pragma unroll
    for (int i = 0; i < 3; ++i) {
        int d = threadIdx.x + i * 256;
        v[i] = x[(long long)n * 768 + d];
        ss += v[i] * v[i];
    }
    ss = blkSum(ss, red);
    bool pad = (sqrtf(ss) <= 1e-6f);
    #pragma unroll
    for (int i = 0; i < 3; ++i) {
        int d = threadIdx.x + i * 256;
        float z = pad ? 0.f : v[i];
        long long o = (long long)n * 768 + d;
        g_ze[o] = z;
        bf16 h0 = __float2bfloat16(z);
        g_zsp[o] = h0;
        g_zsp[NA + o] = __float2bfloat16(z - __bfloat162float(h0));
    }
    if (threadIdx.x == 0) { g_padbias[n] = pad ? NEGB : 0.f; g_zsq[n] = pad ? 0.f : ss; }
}

__global__ __launch_bounds__(256) void cn_kernel(const float* __restrict__ cb) {
    int k = blockIdx.x;
    __shared__ float red[8];
    float ss = 0.f;
    #pragma unroll
    for (int i = 0; i < 3; ++i) {
        int d = threadIdx.x + i * 256;
        float c = cb[(long long)k * 768 + d];
        ss += c * c;
    }
    ss = blkSum(ss, red);
    if (threadIdx.x == 0) g_cn[k] = ss;
}

// ------------- split-plane HMMA GEMM (ldmatrix, K-chunk = CH*16) -------------
// EPI 1: fp32 acc+bias     2: planes relu(acc+bias)   5: planes acc+bias
//     7: planes acc+bias for cols < vbase; V-transpose planes into Vt for cols >= vbase
//     8: fp32 acc/alpha + causal + padbias (fully-masked tiles early-exit)
//     9: fp32 acc/alpha + padbias
//    10: single-plane bf16 acc (coarse VQ dots)
template<int NP, int EPI, int CH>
__global__ __launch_bounds__(256)
void hgemm_k(int M, int N, int K,
             const bf16* __restrict__ Ap, int lda, long long As, long long sA1, long long sA2,
             const bf16* __restrict__ Bp, int ldb, long long Bs, long long sB1, long long sB2,
             float* __restrict__ Cf, bf16* __restrict__ Cb, int ldc, long long Cs,
             long long sC1, long long sC2,
             const float* __restrict__ bias, float alpha, int bdiv, int Nreal,
             bf16* __restrict__ Vt, int vbase)
{
    extern __shared__ __align__(1024) char hsm[];
    const int bz = blockIdx.z;
    const int bo = bz / bdiv, bi = bz % bdiv;
    Ap += bo * sA1 + bi * sA2;
    Bp += bo * sB1 + bi * sB2;
    if (EPI == 1 || EPI == 8 || EPI == 9) Cf += bo * sC1 + bi * sC2;
    else Cb += bo * sC1 + bi * sC2;

    uint32_t sA = s2u(hsm);
    uint32_t sB = sA + (uint32_t)(NP * 2 * TILEB);
    const int t = threadIdx.x, lane = t & 31, warp = t >> 5;
    const int g = lane >> 2, t4 = lane & 3;
    const int bm = blockIdx.y * 128, bn = blockIdx.x * 128;
    const int wm = (warp >> 2) * 64, wn = (warp & 3) * 32;

    const int lane7 = lane & 7, msel = lane >> 3;
    const int aoff = (lane7 + (msel & 1) * 8) * TROW + (msel >> 1) * 8;
    const int boff = (lane7 + (msel >> 1) * 8) * TROW + (msel & 1) * 8;

    float acc[4][4][4];
    #pragma unroll
    for (int a = 0; a < 4; ++a)
        #pragma unroll
        for (int b = 0; b < 4; ++b)
            #pragma unroll
            for (int c = 0; c < 4; ++c) acc[a][b][c] = 0.f;

    const int KC = CH * 16;
    const int G  = CH * 2;
    const int nchunk = K / KC;

    auto stage = [&](int c, int b) {
        const int ko = c * KC;
        const int TOT = NP * 2 * 128 * G;
        #pragma unroll
        for (int i = 0; i < TOT / 256; ++i) {
            int s = t + (i << 8);
            int half = s / (NP * 128 * G);
            int rem  = s - half * (NP * 128 * G);
            int pl = rem / (128 * G);
            int idx = rem - pl * (128 * G);
            int r = idx / G, gg = idx - (idx / G) * G;
            const bf16* src = half
                ? Bp + (long long)pl * Bs + (long long)(bn + r) * ldb + ko + gg * 8
                : Ap + (long long)pl * As + (long long)(bm + r) * lda + ko + gg * 8;
            uint32_t dst = (half ? sB : sA) + (uint32_t)((b * NP + pl) * TILEB + (r * TROW + gg * 8) * 2);
            asm volatile("cp.async.cg.shared.global [%0], [%1], 16;"
                         :: "r"(dst), "l"((const void*)src));
        }
        asm volatile("cp.async.commit_group;" ::: "memory");
    };

    const bool skipmain = (EPI == 8) && (bn + 128 <= bm);

    if (!skipmain) {
        stage(0, 0);
        const int NPROD = (NP == 2) ? 3 : 1;
        const int pa[3] = {0, 0, 1}, pb[3] = {0, 1, 0};

        for (int c = 0; c < nchunk; ++c) {
            const int b = c & 1;
            __syncthreads();
            if (c + 1 < nchunk) {
                stage(c + 1, b ^ 1);
                asm volatile("cp.async.wait_group 1;" ::: "memory");
            } else {
                asm volatile("cp.async.wait_group 0;" ::: "memory");
            }
            __syncthreads();

            #pragma unroll
            for (int p = 0; p < NPROD; ++p) {
                uint32_t ab = sA + (uint32_t)((b * NP + pa[p]) * TILEB);
                uint32_t bb = sB + (uint32_t)((b * NP + pb[p]) * TILEB);
                #pragma unroll
                for (int kh = 0; kh < CH; ++kh) {
                    uint32_t af[4][4], bfr[4][2];
                    #pragma unroll
                    for (int mt = 0; mt < 4; ++mt) {
                        uint32_t addr = ab + (uint32_t)(((wm + mt * 16) * TROW + kh * 16 + aoff) * 2);
                        asm volatile("ldmatrix.sync.aligned.m8n8.x4.shared.b16 {%0,%1,%2,%3}, [%4];"
                            : "=r"(af[mt][0]), "=r"(af[mt][1]), "=r"(af[mt][2]), "=r"(af[mt][3])
                            : "r"(addr));
                    }
                    #pragma unroll
                    for (int ntp = 0; ntp < 2; ++ntp) {
                        uint32_t addr = bb + (uint32_t)(((wn + ntp * 16) * TROW + kh * 16 + boff) * 2);
                        asm volatile("ldmatrix.sync.aligned.m8n8.x4.shared.b16 {%0,%1,%2,%3}, [%4];"
                            : "=r"(bfr[2 * ntp][0]), "=r"(bfr[2 * ntp][1]),
                              "=r"(bfr[2 * ntp + 1][0]), "=r"(bfr[2 * ntp + 1][1])
                            : "r"(addr));
                    }
                    #pragma unroll
                    for (int mt = 0; mt < 4; ++mt)
                        #pragma unroll
                        for (int nt = 0; nt < 4; ++nt)
                            asm volatile(
                                "mma.sync.aligned.m16n8k16.row.col.f32.bf16.bf16.f32 "
                                "{%0,%1,%2,%3}, {%4,%5,%6,%7}, {%8,%9}, {%0,%1,%2,%3};"
                                : "+f"(acc[mt][nt][0]), "+f"(acc[mt][nt][1]),
                                  "+f"(acc[mt][nt][2]), "+f"(acc[mt][nt][3])
                                : "r"(af[mt][0]), "r"(af[mt][1]), "r"(af[mt][2]), "r"(af[mt][3]),
                                  "r"(bfr[nt][0]), "r"(bfr[nt][1]));
                }
            }
        }
    }

    const int padbase = bo * 512;
    #pragma unroll
    for (int mt = 0; mt < 4; ++mt) {
        int r0 = bm + wm + mt * 16 + g;
        #pragma unroll
        for (int nt = 0; nt < 4; ++nt) {
            int c0 = bn + wn + nt * 8 + t4 * 2;
            float v0 = acc[mt][nt][0], v1 = acc[mt][nt][1];
            float v2 = acc[mt][nt][2], v3 = acc[mt][nt][3];
            if (EPI == 1 || EPI == 2 || EPI == 5 || EPI == 7) {
                float b0 = bias[c0], b1 = bias[c0 + 1];
                v0 += b0; v1 += b1; v2 += b0; v3 += b1;
            }
            if (EPI == 2) {
                v0 = fmaxf(v0, 0.f); v1 = fmaxf(v1, 0.f);
                v2 = fmaxf(v2, 0.f); v3 = fmaxf(v3, 0.f);
            }
            if (EPI == 8 || EPI == 9) {
                v0 = __fdiv_rn(v0, alpha); v1 = __fdiv_rn(v1, alpha);
                v2 = __fdiv_rn(v2, alpha); v3 = __fdiv_rn(v3, alpha);
                if (EPI == 8) {
                    if (c0 < r0)         v0 += NEGB;
                    if (c0 + 1 < r0)     v1 += NEGB;
                    if (c0 < r0 + 8)     v2 += NEGB;
                    if (c0 + 1 < r0 + 8) v3 += NEGB;
                }
                float b0 = bias[padbase + c0], b1 = bias[padbase + c0 + 1];
                v0 += b0; v1 += b1; v2 += b0; v3 += b1;
            }
            if (EPI == 1 || EPI == 8 || EPI == 9) {
                *(float2*)&Cf[(long long)r0 * ldc + c0]       = make_float2(v0, v1);
                *(float2*)&Cf[(long long)(r0 + 8) * ldc + c0] = make_float2(v2, v3);
            } else if (EPI == 10) {
                bf162 q0; q0.x = __float2bfloat16(v0); q0.y = __float2bfloat16(v1);
                bf162 q1; q1.x = __float2bfloat16(v2); q1.y = __float2bfloat16(v3);
                *(bf162*)&Cb[(long long)r0 * ldc + c0]       = q0;
                *(bf162*)&Cb[(long long)(r0 + 8) * ldc + c0] = q1;
            } else if (EPI == 7 && c0 >= vbase) {
                int col = c0 - vbase;
                int hh = col / 96, nn = col - hh * 96;
                int bb2 = r0 >> 9, tk = r0 & 511;
                long long base = (long long)(bb2 * 8 + hh) * 65536 + (long long)nn * 512 + tk;
                bf16 x0 = __float2bfloat16(v0);
                Vt[base]           = x0; Vt[NVT + base]           = __float2bfloat16(v0 - __bfloat162float(x0));
                bf16 x1 = __float2bfloat16(v1);
                Vt[base + 512]     = x1; Vt[NVT + base + 512]     = __float2bfloat16(v1 - __bfloat162float(x1));
                bf16 x2 = __float2bfloat16(v2);
                Vt[base + 8]       = x2; Vt[NVT + base + 8]       = __float2bfloat16(v2 - __bfloat162float(x2));
                bf16 x3 = __float2bfloat16(v3);
                Vt[base + 512 + 8] = x3; Vt[NVT + base + 512 + 8] = __float2bfloat16(v3 - __bfloat162float(x3));
            } else {
                splitWr(Cb, Cs, (long long)r0 * ldc + c0, v0, v1);
                splitWr(Cb, Cs, (long long)(r0 + 8) * ldc + c0, v2, v3);
            }
        }
    }
}

// ------------- fused softmax+PV: atsp = softmax(scores) @ V -------------
__global__ __launch_bounds__(256)
void pvfused_k(int causal)
{
    extern __shared__ __align__(1024) char hsm[];
    const int bh = blockIdx.z;
    const int bo = bh >> 3, bi = bh & 7;
    const int bm = blockIdx.y * 128;
    const float* S = g_scores + (long long)bo * 2097152 + (long long)bi * 262144
                   + (long long)bm * 512;
    const bf16* Bp = g_vtsp + (long long)bh * 65536;
    bf16* C = g_atsp + (long long)bo * (512LL * 768) + bi * 96;

    uint32_t sA = s2u(hsm);
    uint32_t sB = sA + 4 * TILEB;
    float* rowsum = (float*)(hsm + 8 * TILEB);
    const int t = threadIdx.x, lane = t & 31, warp = t >> 5;
    const int g = lane >> 2, t4 = lane & 3;
    const int wm = (warp >> 2) * 64, wn = (warp & 3) * 32;
    const int lane7 = lane & 7, msel = lane >> 3;
    const int aoff = (lane7 + (msel & 1) * 8) * TROW + (msel >> 1) * 8;
    const int boff = (lane7 + (msel >> 1) * 8) * TROW + (msel & 1) * 8;

    float acc[4][4][4];
    #pragma unroll
    for (int a = 0; a < 4; ++a)
        #pragma unroll
        for (int b = 0; b < 4; ++b)
            #pragma unroll
            for (int c = 0; c < 4; ++c) acc[a][b][c] = 0.f;

    const int ar = t >> 1, ach = (t & 1) << 4;
    float asum = 0.f;

    auto stageB = [&](int c, int b) {
        const int ko = c << 5;
        #pragma unroll
        for (int i = 0; i < 4; ++i) {
            int s2 = t + (i << 8);
            int pl = s2 >> 9, idx = s2 & 511;
            int r = idx >> 2, gg = idx & 3;
            const bf16* src = Bp + (long long)pl * NVT + (long long)r * 512 + ko + gg * 8;
            uint32_t dst = sB + (uint32_t)((b * 2 + pl) * TILEB + (r * TROW + gg * 8) * 2);
            asm volatile("cp.async.cg.shared.global [%0], [%1], 16;"
                         :: "r"(dst), "l"((const void*)src));
        }
        asm volatile("cp.async.commit_group;" ::: "memory");
    };
    auto stageA = [&](int c, int b) {
        const int ko = c << 5;
        const float* srow = S + (long long)ar * 512 + ko + ach;
        uint32_t d0 = sA + (uint32_t)((b * 2) * TILEB + (ar * TROW + ach) * 2);
        uint32_t d1 = d0 + (uint32_t)TILEB;
        #pragma unroll
        for (int j = 0; j < 16; j += 2) {
            float e0 = expf(srow[j]);
            float e1 = expf(srow[j + 1]);
            asum += e0 + e1;
            bf16 h0 = __float2bfloat16(e0), h1 = __float2bfloat16(e1);
            bf162 q0; q0.x = h0; q0.y = h1;
            bf162 q1; q1.x = __float2bfloat16(e0 - __bfloat162float(h0));
            q1.y = __float2bfloat16(e1 - __bfloat162float(h1));
            asm volatile("st.shared.b32 [%0], %1;" :: "r"(d0 + (uint32_t)(j * 2)), "r"(*(uint32_t*)&q0));
            asm volatile("st.shared.b32 [%0], %1;" :: "r"(d1 + (uint32_t)(j * 2)), "r"(*(uint32_t*)&q1));
        }
    };

    const int c_start = causal ? (bm >> 5) : 0;
    stageB(c_start, c_start & 1);
    stageA(c_start, c_start & 1);
    const int pa[3] = {0, 0, 1}, pb[3] = {0, 1, 0};

    for (int c = c_start; c < 16; ++c) {
        const int b = c & 1;
        __syncthreads();
        if (c + 1 < 16) {
            stageB(c + 1, b ^ 1);
            stageA(c + 1, b ^ 1);
            asm volatile("cp.async.wait_group 1;" ::: "memory");
        } else {
            asm volatile("cp.async.wait_group 0;" ::: "memory");
        }
        __syncthreads();

        #pragma unroll
        for (int p = 0; p < 3; ++p) {
            uint32_t ab = sA + (uint32_t)((b * 2 + pa[p]) * TILEB);
            uint32_t bb = sB + (uint32_t)((b * 2 + pb[p]) * TILEB);
            #pragma unroll
            for (int kh = 0; kh < 2; ++kh) {
                uint32_t af[4][4], bfr[4][2];
                #pragma unroll
                for (int mt = 0; mt < 4; ++mt) {
                    uint32_t addr = ab + (uint32_t)(((wm + mt * 16) * TROW + kh * 16 + aoff) * 2);
                    asm volatile("ldmatrix.sync.aligned.m8n8.x4.shared.b16 {%0,%1,%2,%3}, [%4];"
                        : "=r"(af[mt][0]), "=r"(af[mt][1]), "=r"(af[mt][2]), "=r"(af[mt][3])
                        : "r"(addr));
                }
                #pragma unroll
                for (int ntp = 0; ntp < 2; ++ntp) {
                    uint32_t addr = bb + (uint32_t)(((wn + ntp * 16) * TROW + kh * 16 + boff) * 2);
                    asm volatile("ldmatrix.sync.aligned.m8n8.x4.shared.b16 {%0,%1,%2,%3}, [%4];"
                        : "=r"(bfr[2 * ntp][0]), "=r"(bfr[2 * ntp][1]),
                          "=r"(bfr[2 * ntp + 1][0]), "=r"(bfr[2 * ntp + 1][1])
                        : "r"(addr));
                }
                #pragma unroll
                for (int mt = 0; mt < 4; ++mt)
                    #pragma unroll
                    for (int nt = 0; nt < 4; ++nt)
                        asm volatile(
                            "mma.sync.aligned.m16n8k16.row.col.f32.bf16.bf16.f32 "
                            "{%0,%1,%2,%3}, {%4,%5,%6,%7}, {%8,%9}, {%0,%1,%2,%3};"
                            : "+f"(acc[mt][nt][0]), "+f"(acc[mt][nt][1]),
                              "+f"(acc[mt][nt][2]), "+f"(acc[mt][nt][3])
                            : "r"(af[mt][0]), "r"(af[mt][1]), "r"(af[mt][2]), "r"(af[mt][3]),
                              "r"(bfr[nt][0]), "r"(bfr[nt][1]));
            }
        }
    }

    float other = __shfl_xor_sync(0xffffffffu, asum, 1);
    if ((t & 1) == 0) rowsum[ar] = asum + other;
    __syncthreads();

    #pragma unroll
    for (int mt = 0; mt < 4; ++mt) {
        int rl = wm + mt * 16 + g;
        float rv0 = 1.0f / rowsum[rl];
        float rv1 = 1.0f / rowsum[rl + 8];
        int r0 = bm + rl;
        #pragma unroll
        for (int nt = 0; nt < 4; ++nt) {
            int c0 = wn + nt * 8 + t4 * 2;
            if (c0 < 96) {
                splitWr(C, NA, (long long)r0 * 768 + c0,
                        acc[mt][nt][0] * rv0, acc[mt][nt][1] * rv0);
                splitWr(C, NA, (long long)(r0 + 8) * 768 + c0,
                        acc[mt][nt][2] * rv1, acc[mt][nt][3] * rv1);
            }
        }
    }
}

// ------------- fp32 -> 2 bf16 planes (explicit plane stride) -------------
__global__ __launch_bounds__(256) void split2_k(const float* __restrict__ x,
                                                bf16* __restrict__ p, long long n, long long stride) {
    long long i = (long long)blockIdx.x * 256 + threadIdx.x;
    if (i >= n) return;
    float v = x[i];
    bf16 h0 = __float2bfloat16(v);
    p[i] = h0;
    p[stride + i] = __float2bfloat16(v - __bfloat162float(h0));
}

// ------------- coarse top-16 candidate set (bf16 dots) -------------
__global__ __launch_bounds__(256) void topk16_k() {
    int n = blockIdx.x;
    const bf16* drow = g_dotb + (long long)n * KCB;
    float zs = g_zsq[n];
    int t = threadIdx.x;
    float v[32];
    #pragma unroll
    for (int j = 0; j < 32; ++j) {
        int k = j * 256 + t;
        v[j] = (zs + g_cn[k]) - 2.0f * __bfloat162float(drow[k]);
    }
    __shared__ float sv[8]; __shared__ int si[8]; __shared__ int sbi;
    const float INF = __int_as_float(0x7f800000);
    for (int r = 0; r < 16; ++r) {
        float lv = INF; int li = 0x7fffffff;
        #pragma unroll
        for (int j = 0; j < 32; ++j) {
            int k = j * 256 + t;
            if (v[j] < lv) { lv = v[j]; li = k; }
        }
        #pragma unroll
        for (int o = 16; o; o >>= 1) {
            float ov = __shfl_xor_sync(0xffffffffu, lv, o);
            int   oi = __shfl_xor_sync(0xffffffffu, li, o);
            if (ov < lv || (ov == lv && oi < li)) { lv = ov; li = oi; }
        }
        if ((t & 31) == 0) { sv[t >> 5] = lv; si[t >> 5] = li; }
        __syncthreads();
        if (t == 0) {
            float bv = sv[0]; int bi2 = si[0];
            #pragma unroll
            for (int w = 1; w < 8; ++w)
                if (sv[w] < bv || (sv[w] == bv && si[w] < bi2)) { bv = sv[w]; bi2 = si[w]; }
            g_ci[n * 16 + r] = bi2;
            sbi = bi2;
        }
        __syncthreads();
        int bi2 = sbi;
        if ((bi2 & 255) == t) v[bi2 >> 8] = INF;
        __syncthreads();
    }
}

// ------------- exact fp32 rerank of 16 candidates -> top-10 -------------
__global__ __launch_bounds__(256) void rerank_k(const float* __restrict__ cb) {
    int n = blockIdx.x;
    int t = threadIdx.x, w = t >> 5, lane = t & 31;
    __shared__ float sd[16]; __shared__ int sk[16];
    for (int c = w; c < 16; c += 8) {
        int k = g_ci[n * 16 + c];
        const float* zr = g_ze + (long long)n * 768;
        const float* cr = cb + (long long)k * 768;
        float dot = 0.f;
        for (int i = lane * 4; i < 768; i += 128) {
            float4 a = *(const float4*)&zr[i];
            float4 b = *(const float4*)&cr[i];
            dot = fmaf(a.x, b.x, dot); dot = fmaf(a.y, b.y, dot);
            dot = fmaf(a.z, b.z, dot); dot = fmaf(a.w, b.w, dot);
        }
        #pragma unroll
        for (int o = 16; o; o >>= 1) dot += __shfl_xor_sync(0xffffffffu, dot, o);
        if (lane == 0) {
            sd[c] = __fsub_rn(__fadd_rn(g_zsq[n], g_cn[k]), __fmul_rn(2.0f, dot));
            sk[c] = k;
        }
    }
    __syncthreads();
    if (t == 0) {
        bool used[16];
        #pragma unroll
        for (int i = 0; i < 16; ++i) used[i] = false;
        for (int r = 0; r < 10; ++r) {
            float bd = __int_as_float(0x7f800000); int bk = 0x7fffffff, bc = 0;
            #pragma unroll
            for (int c = 0; c < 16; ++c)
                if (!used[c] && (sd[c] < bd || (sd[c] == bd && sk[c] < bk))) {
                    bd = sd[c]; bk = sk[c]; bc = c;
                }
            used[bc] = true;
            g_topd[n * 10 + r] = -bd;
            g_topi[n * 10 + r] = bk;
        }
    }
}

// ------------- threefry + gumbel sample -------------
__device__ __forceinline__ unsigned rotl32(unsigned x, int r) { return (x << r) | (x >> (32 - r)); }
__device__ __forceinline__ void tf4(unsigned& x0, unsigned& x1, int r0, int r1, int r2, int r3) {
    x0 += x1; x1 = rotl32(x1, r0); x1 ^= x0;
    x0 += x1; x1 = rotl32(x1, r1); x1 ^= x0;
    x0 += x1; x1 = rotl32(x1, r2); x1 ^= x0;
    x0 += x1; x1 = rotl32(x1, r3); x1 ^= x0;
}
__device__ __forceinline__ void threefry(unsigned c0, unsigned c1, unsigned& o0, unsigned& o1) {
    const unsigned k0 = 0u, k1 = 42u, k2 = 0x1BD11BDAu ^ 0u ^ 42u;
    unsigned x0 = c0 + k0, x1 = c1 + k1;
    tf4(x0, x1, 13, 15, 26, 6);  x0 += k1; x1 += k2 + 1u;
    tf4(x0, x1, 17, 29, 16, 24); x0 += k2; x1 += k0 + 2u;
    tf4(x0, x1, 13, 15, 26, 6);  x0 += k0; x1 += k1 + 3u;
    tf4(x0, x1, 17, 29, 16, 24); x0 += k1; x1 += k2 + 4u;
    tf4(x0, x1, 13, 15, 26, 6);  x0 += k2; x1 += k0 + 5u;
    o0 = x0; o1 = x1;
}
__global__ __launch_bounds__(256) void sample_k() {
    int n = blockIdx.x * 256 + threadIdx.x;
    float best = -__int_as_float(0x7f800000); int bj = 0;
    #pragma unroll
    for (int j = 0; j < 10; ++j) {
        unsigned m = (unsigned)n * 10u + (unsigned)j, o0, o1;
        threefry(0u, m, o0, o1);
        unsigned bits = o0 ^ o1;
        float f = __uint_as_float((bits >> 9) | 0x3f800000u) - 1.0f;
        float u = fmaxf(1e-10f, __fadd_rn(f, 1e-10f));
        float gum = -logf(-logf(u));
        float val = __fadd_rn(g_topd[n * 10 + j], gum);
        if (val > best) { best = val; bj = j; }
    }
    g_enc[n] = g_topi[n * 10 + bj];
}

// ------------- quantize (+fused split of h) -------------
__global__ __launch_bounds__(256) void quant_k(const float* __restrict__ cb) {
    int n = blockIdx.x;
    long long idx = g_enc[n];
    #pragma unroll
    for (int i = 0; i < 3; ++i) {
        int d = threadIdx.x + i * 256;
        long long o = (long long)n * 768 + d;
        float z = g_ze[o];
        float q = cb[idx * 768 + d];
        float hv = __fadd_rn(z, __fsub_rn(q, z));
        g_h[o] = hv;
        bf16 h0 = __float2bfloat16(hv);
        g_hsp[o] = h0;
        g_hsp[NA + o] = __float2bfloat16(hv - __bfloat162float(h0));
    }
}

// ------------- residual + LayerNorm (+fused split of h) -------------
__global__ __launch_bounds__(256) void addln_k(float* __restrict__ h, const float* __restrict__ res,
                                               const float* __restrict__ g, const float* __restrict__ b) {
    int n = blockIdx.x;
    __shared__ float red[8];
    float v[3]; float s = 0.f;
    #pragma unroll
    for (int i = 0; i < 3; ++i) {
        int d = threadIdx.x + i * 256;
        v[i] = h[(long long)n * 768 + d] + res[(long long)n * 768 + d];
        s += v[i];
    }
    s = blkSum(s, red);
    float mean = s * (1.0f / 768.0f);
    float vs = 0.f;
    #pragma unroll
    for (int i = 0; i < 3; ++i) { float d0 = v[i] - mean; vs += d0 * d0; }
    vs = blkSum(vs, red);
    float inv = __fdiv_rn(1.0f, sqrtf(vs * (1.0f / 768.0f) + 1e-5f));
    #pragma unroll
    for (int i = 0; i < 3; ++i) {
        int d = threadIdx.x + i * 256;
        long long o = (long long)n * 768 + d;
        float hv = (v[i] - mean) * inv * g[d] + b[d];
        h[o] = hv;
        bf16 h0 = __float2bfloat16(hv);
        g_hsp[o] = h0;
        g_hsp[NA + o] = __float2bfloat16(hv - __bfloat162float(h0));
    }
}

// ------------- host side -------------
struct HArgs {
    int M, N, K;
    const bf16 *A; int lda; long long As, sA1, sA2;
    const bf16 *B; int ldb; long long Bs, sB1, sB2;
    float* Cf; bf16* Cb; int ldc; long long Cs, sC1, sC2;
    cfp bias; float alpha; int Z, bdiv, Nreal;
    bf16* Vt; int vbase;
};
static void hgemm(int np, int epi, const HArgs& a) {
    dim3 g(a.N / 128, a.M / 128, a.Z);
    size_t sm = (size_t)np * 4 * TILEB;
    int ch = (a.K % 48 == 0) ? 3 : 2;
#define HG(NPV,EV,CV) hgemm_k<NPV,EV,CV><<<g,256,sm>>>(a.M,a.N,a.K,a.A,a.lda,a.As,a.sA1,a.sA2, \
    a.B,a.ldb,a.Bs,a.sB1,a.sB2,a.Cf,a.Cb,a.ldc,a.Cs,a.sC1,a.sC2,a.bias,a.alpha,a.bdiv,a.Nreal,a.Vt,a.vbase)
    if (np == 1) { HG(1,10,3); return; }
    if (ch == 3) {
        switch (epi) {
            case 1: HG(2,1,3); break;  case 2: HG(2,2,3); break;
            case 5: HG(2,5,3); break;  case 7: HG(2,7,3); break;
            case 8: HG(2,8,3); break;  case 9: HG(2,9,3); break;
            default: HG(2,1,3); break;
        }
    } else {
        HG(2,1,2);   // only ff2 (K=2048) takes this path
    }
#undef HG
}
static void split2(cfp x, bf16* p, long long n, long long stride) {
    split2_k<<<(unsigned)((n + 255) / 256), 256>>>(x, p, n, stride);
}

extern "C" void kernel_launch(void* const* d_in, const int* in_sizes, int n_in,
                              void* d_out, int out_size) {
    cfp x     = (cfp)d_in[0];
    cfp cb    = (cfp)d_in[1];
    cfp sa_in_w = (cfp)d_in[2],  sa_in_b = (cfp)d_in[3];
    cfp sa_out_w= (cfp)d_in[4],  sa_out_b= (cfp)d_in[5];
    cfp ca_in_w = (cfp)d_in[6],  ca_in_b = (cfp)d_in[7];
    cfp ca_out_w= (cfp)d_in[8],  ca_out_b= (cfp)d_in[9];
    cfp ln1_g = (cfp)d_in[10], ln1_b = (cfp)d_in[11];
    cfp ln2_g = (cfp)d_in[12], ln2_b = (cfp)d_in[13];
    cfp ln3_g = (cfp)d_in[14], ln3_b = (cfp)d_in[15];
    cfp ff_w1 = (cfp)d_in[16], ff_b1 = (cfp)d_in[17];
    cfp ff_w2 = (cfp)d_in[18], ff_b2 = (cfp)d_in[19];
    cfp out_w = (cfp)d_in[20], out_b = (cfp)d_in[21];
    float* out = (float*)d_out;

    cudaFuncSetAttribute(hgemm_k<1,10,3>, cudaFuncAttributeMaxDynamicSharedMemorySize, 4 * TILEB);
    cudaFuncSetAttribute(hgemm_k<2,1,3>, cudaFuncAttributeMaxDynamicSharedMemorySize, 8 * TILEB);
    cudaFuncSetAttribute(hgemm_k<2,2,3>, cudaFuncAttributeMaxDynamicSharedMemorySize, 8 * TILEB);
    cudaFuncSetAttribute(hgemm_k<2,5,3>, cudaFuncAttributeMaxDynamicSharedMemorySize, 8 * TILEB);
    cudaFuncSetAttribute(hgemm_k<2,7,3>, cudaFuncAttributeMaxDynamicSharedMemorySize, 8 * TILEB);
    cudaFuncSetAttribute(hgemm_k<2,8,3>, cudaFuncAttributeMaxDynamicSharedMemorySize, 8 * TILEB);
    cudaFuncSetAttribute(hgemm_k<2,9,3>, cudaFuncAttributeMaxDynamicSharedMemorySize, 8 * TILEB);
    cudaFuncSetAttribute(hgemm_k<2,1,2>, cudaFuncAttributeMaxDynamicSharedMemorySize, 8 * TILEB);
    cudaFuncSetAttribute(pvfused_k, cudaFuncAttributeMaxDynamicSharedMemorySize, PVSMEM);

    float *ze, *h, *proj, *scores, *padb;
    bf16 *dotb, *zsp, *hsp, *atsp, *fsp, *qsp, *cbsp, *vtsp, *wall;
    cudaGetSymbolAddress((void**)&ze, g_ze);
    cudaGetSymbolAddress((void**)&h, g_h);
    cudaGetSymbolAddress((void**)&proj, g_proj);
    cudaGetSymbolAddress((void**)&scores, g_scores);
    cudaGetSymbolAddress((void**)&padb, g_padbias);
    cudaGetSymbolAddress((void**)&dotb, g_dotb);
    cudaGetSymbolAddress((void**)&zsp, g_zsp);
    cudaGetSymbolAddress((void**)&hsp, g_hsp);
    cudaGetSymbolAddress((void**)&atsp, g_atsp);
    cudaGetSymbolAddress((void**)&fsp, g_fsp);
    cudaGetSymbolAddress((void**)&qsp, g_qsp);
    cudaGetSymbolAddress((void**)&cbsp, g_cbsp);
    cudaGetSymbolAddress((void**)&vtsp, g_vtsp);
    cudaGetSymbolAddress((void**)&wall, g_wall);

    const float sc = sqrtf(96.f);

    // ---- pre-split ALL weights into the wall (plane stride NW) ----
    split2(sa_in_w,  wall + W_SIW, 10616832LL, NW);
    split2(sa_out_w, wall + W_SOW, 3538944LL,  NW);
    split2(ca_in_w,  wall + W_CIW, 10616832LL, NW);
    split2(ca_out_w, wall + W_COW, 3538944LL,  NW);
    split2(ff_w1,    wall + W_W1,  9437184LL,  NW);
    split2(ff_w2,    wall + W_W2,  9437184LL,  NW);
    split2(out_w,    wall + W_OW,  589824LL,   NW);

    // ---- VQ: coarse bf16 (single-plane dots) -> exact rerank ----
    ze_kernel<<<8192, 256>>>(x);
    cn_kernel<<<8192, 256>>>(cb);
    split2(cb, cbsp, NA, NA);
    { HArgs a = {8192, 8192, 768, zsp, 768, NA, 0, 0, cbsp, 768, NA, 0, 0,
                 nullptr, dotb, 8192, 0, 0, 0, nullptr, 1.f, 1, 1, 0, nullptr, 0};
      hgemm(1, 10, a); }
    topk16_k<<<8192, 256>>>();
    rerank_k<<<8192, 256>>>(cb);
    sample_k<<<32, 256>>>();
    quant_k<<<8192, 256>>>(cb);

    for (int l = 0; l < 6; ++l) {
        const bf16* siw = wall + W_SIW + (long long)l * 2304 * 768;
        const bf16* sow = wall + W_SOW + (long long)l * 768 * 768;
        const bf16* ciw = wall + W_CIW + (long long)l * 2304 * 768;
        const bf16* cow = wall + W_COW + (long long)l * 768 * 768;
        const bf16* w1  = wall + W_W1  + (long long)l * 2048 * 768;
        const bf16* w2  = wall + W_W2  + (long long)l * 768 * 2048;
        cfp sib = sa_in_b + l * 2304, sob = sa_out_b + l * 768;
        cfp cib = ca_in_b + l * 2304, cob = ca_out_b + l * 768;
        cfp b1 = ff_b1 + l * 2048, b2 = ff_b2 + l * 768;

        for (int att = 0; att < 2; ++att) {
            if (att == 0) {
                HArgs a = {8192, 2304, 768, hsp, 768, NA, 0, 0, siw, 768, NW, 0, 0,
                           nullptr, qsp, 2304, NQ, 0, 0, sib, 0.f, 1, 1, 0, vtsp, 1536};
                hgemm(2, 7, a);
            } else {
                HArgs aq = {8192, 768, 768, hsp, 768, NA, 0, 0, ciw, 768, NW, 0, 0,
                            nullptr, qsp, 2304, NQ, 0, 0, cib, 0.f, 1, 1, 0, nullptr, 0};
                hgemm(2, 5, aq);
                HArgs akv = {8192, 1536, 768, zsp, 768, NA, 0, 0, ciw + 768LL * 768, 768, NW, 0, 0,
                             nullptr, qsp + 768, 2304, NQ, 0, 0, cib + 768, 0.f, 1, 1, 0, vtsp, 768};
                hgemm(2, 7, akv);
            }
            // scores = q@k^T / sc + mask  (fp32; EPI8 early-exits masked tiles)
            { HArgs a = {512, 512, 96, qsp, 2304, NQ, 512LL * 2304, 96,
                         qsp + 768, 2304, NQ, 512LL * 2304, 96,
                         scores, nullptr, 512, 0, 8LL * 262144, 262144,
                         padb, sc, 128, 8, 0, nullptr, 0};
              hgemm(2, att == 0 ? 8 : 9, a); }
            // fused softmax + PV -> atsp planes
            pvfused_k<<<dim3(1, 4, 128), 256, PVSMEM>>>(att == 0 ? 1 : 0);
            // out projection + addln
            { HArgs a = {8192, 768, 768, atsp, 768, NA, 0, 0, att == 0 ? sow : cow, 768, NW, 0, 0,
                         proj, nullptr, 768, 0, 0, 0, att == 0 ? sob : cob, 0.f, 1, 1, 0, nullptr, 0};
              hgemm(2, 1, a); }
            addln_k<<<8192, 256>>>(h, proj,
                (att == 0 ? ln1_g : ln2_g) + l * 768, (att == 0 ? ln1_b : ln2_b) + l * 768);
        }

        // ---- feed-forward ----
        { HArgs a = {8192, 2048, 768, hsp, 768, NA, 0, 0, w1, 768, NW, 0, 0,
                     nullptr, fsp, 2048, NF, 0, 0, b1, 0.f, 1, 1, 0, nullptr, 0};
          hgemm(2, 2, a); }
        { HArgs a = {8192, 768, 2048, fsp, 2048, NF, 0, 0, w2, 2048, NW, 0, 0,
                     proj, nullptr, 768, 0, 0, 0, b2, 0.f, 1, 1, 0, nullptr, 0};
          hgemm(2, 1, a); }
        addln_k<<<8192, 256>>>(h, proj, ln3_g + l * 768, ln3_b + l * 768);
    }

    // ---- output projection ----
    { HArgs a = {8192, 768, 768, hsp, 768, NA, 0, 0, wall + W_OW, 768, NW, 0, 0,
                 out, nullptr, 768, 0, 0, 0, out_b, 0.f, 1, 1, 0, nullptr, 0};
      hgemm(2, 1, a); }
}

// round 16
// speedup vs baseline: 1.0320x; 1.0320x over previous
#include <cuda_runtime.h>
#include <cuda_bf16.h>
#include <stdint.h>
#include <math.h>

#define NTOK 8192
#define KCB  8192
#define NEGB (-1e9f)

typedef __nv_bfloat16 bf16;
typedef __nv_bfloat162 bf162;
typedef const float* cfp;

// plane strides
#define NA  (8192LL*768)
#define NF  (8192LL*2048)
#define NQ  (8192LL*2304)
#define NP_ (33554432LL)          // prob plane: 128*512*512
#define NVT (8388608LL)           // vT plane: 128*128*512

// pre-split weight wall: offsets (elems) and total
#define W_SIW 0LL
#define W_SOW 10616832LL
#define W_CIW 14155776LL
#define W_COW 24772608LL
#define W_W1  28311552LL
#define W_W2  37748736LL
#define W_OW  47185920LL
#define NW    47775744LL

// smem tile: 128 rows x 56 elems (112B stride, conflict-free for ldmatrix)
#define TROW 56
#define TILEB (128*TROW*2)        // 14336 bytes

// ------------- static device scratch -------------
static __device__ float g_ze[NTOK*768];
static __device__ float g_h[NTOK*768];
static __device__ float g_proj[NTOK*768];
static __device__ float g_scores[128*512*512];
static __device__ float g_cn[KCB];
static __device__ float g_zsq[NTOK];
static __device__ float g_padbias[NTOK];
static __device__ float g_topd[NTOK*10];
static __device__ int   g_topi[NTOK*10];
static __device__ int   g_enc[NTOK];
static __device__ int   g_ci[NTOK*16];
// bf16 buffers
static __device__ __align__(16) bf16 g_dotb[(long long)NTOK*KCB];   // coarse dots, single plane
static __device__ __align__(16) bf16 g_zsp[2*NA];
static __device__ __align__(16) bf16 g_hsp[2*NA];
static __device__ __align__(16) bf16 g_atsp[2*NA];
static __device__ __align__(16) bf16 g_fsp[2*NF];
static __device__ __align__(16) bf16 g_qsp[2*NQ];
static __device__ __align__(16) bf16 g_cbsp[2*NA];
static __device__ __align__(16) bf16 g_psp[2*NP_];
static __device__ __align__(16) bf16 g_vtsp[2*NVT];                 // rows n>=96 stay zero
static __device__ __align__(16) bf16 g_wall[2*NW];

// ------------- helpers -------------
__device__ __forceinline__ float blkSum(float v, float* red) {
    #pragma unroll
    for (int o = 16; o; o >>= 1) v += __shfl_xor_sync(0xffffffffu, v, o);
    if ((threadIdx.x & 31) == 0) red[threadIdx.x >> 5] = v;
    __syncthreads();
    float s = red[0];
    #pragma unroll
    for (int i = 1; i < 8; ++i) s += red[i];
    __syncthreads();
    return s;
}
__device__ __forceinline__ uint32_t s2u(const void* p) {
    uint32_t a;
    asm("{ .reg .u64 t; cvta.to.shared.u64 t, %1; cvt.u32.u64 %0, t; }" : "=r"(a) : "l"(p));
    return a;
}
__device__ __forceinline__ void splitWr(bf16* Cb, long long Cs, long long off, float a, float b) {
    bf16 h0 = __float2bfloat16(a), h1 = __float2bfloat16(b);
    bf162 p0; p0.x = h0; p0.y = h1;
    bf162 p1; p1.x = __float2bfloat16(a - __bfloat162float(h0));
    p1.y = __float2bfloat16(b - __bfloat162float(h1));
    *(bf162*)&Cb[off] = p0;
    *(bf162*)&Cb[Cs + off] = p1;
}

// ------------- z_e, pad, |z|^2 (+fused split) -------------
__global__ __launch_bounds__(256) void ze_kernel(const float* __restrict__ x) {
    int n = blockIdx.x;
    __shared__ float red[8];
    float v[3]; float ss = 0.f;
    #pragma unroll
    for (int i = 0; i < 3; ++i) {
        int d = threadIdx.x + i * 256;
        v[i] = x[(long long)n * 768 + d];
        ss += v[i] * v[i];
    }
    ss = blkSum(ss, red);
    bool pad = (sqrtf(ss) <= 1e-6f);
    #pragma unroll
    for (int i = 0; i < 3; ++i) {
        int d = threadIdx.x + i * 256;
        float z = pad ? 0.f : v[i];
        long long o = (long long)n * 768 + d;
        g_ze[o] = z;
        bf16 h0 = __float2bfloat16(z);
        g_zsp[o] = h0;
        g_zsp[NA + o] = __float2bfloat16(z - __bfloat162float(h0));
    }
    if (threadIdx.x == 0) { g_padbias[n] = pad ? NEGB : 0.f; g_zsq[n] = pad ? 0.f : ss; }
}

__global__ __launch_bounds__(256) void cn_kernel(const float* __restrict__ cb) {
    int k = blockIdx.x;
    __shared__ float red[8];
    float ss = 0.f;
    #pragma unroll
    for (int i = 0; i < 3; ++i) {
        int d = threadIdx.x + i * 256;
        float c = cb[(long long)k * 768 + d];
        ss += c * c;
    }
    ss = blkSum(ss, red);
    if (threadIdx.x == 0) g_cn[k] = ss;
}

// ------------- split-plane HMMA GEMM (ldmatrix, K-chunk = CH*16) -------------
// EPI 1: fp32 acc+bias     2: planes relu(acc+bias)   5: planes acc+bias
//     6: planes acc, cols < Nreal only (causal=1: skip all-zero A chunks, bitwise identical)
//     7: planes acc+bias for cols < vbase; V-transpose planes into Vt for cols >= vbase
//     8: fp32 acc/alpha + causal + padbias (fully-masked tiles early-exit)
//     9: fp32 acc/alpha + padbias
//    10: single-plane bf16 acc (coarse VQ dots)
template<int NP, int EPI, int CH>
__global__ __launch_bounds__(256)
void hgemm_k(int M, int N, int K,
             const bf16* __restrict__ Ap, int lda, long long As, long long sA1, long long sA2,
             const bf16* __restrict__ Bp, int ldb, long long Bs, long long sB1, long long sB2,
             float* __restrict__ Cf, bf16* __restrict__ Cb, int ldc, long long Cs,
             long long sC1, long long sC2,
             const float* __restrict__ bias, float alpha, int bdiv, int Nreal,
             bf16* __restrict__ Vt, int vbase, int causal)
{
    extern __shared__ __align__(1024) char hsm[];
    const int bz = blockIdx.z;
    const int bo = bz / bdiv, bi = bz % bdiv;
    Ap += bo * sA1 + bi * sA2;
    Bp += bo * sB1 + bi * sB2;
    if (EPI == 1 || EPI == 8 || EPI == 9) Cf += bo * sC1 + bi * sC2;
    else Cb += bo * sC1 + bi * sC2;

    uint32_t sA = s2u(hsm);
    uint32_t sB = sA + (uint32_t)(NP * 2 * TILEB);
    const int t = threadIdx.x, lane = t & 31, warp = t >> 5;
    const int g = lane >> 2, t4 = lane & 3;
    const int bm = blockIdx.y * 128, bn = blockIdx.x * 128;
    const int wm = (warp >> 2) * 64, wn = (warp & 3) * 32;

    const int lane7 = lane & 7, msel = lane >> 3;
    const int aoff = (lane7 + (msel & 1) * 8) * TROW + (msel >> 1) * 8;
    const int boff = (lane7 + (msel >> 1) * 8) * TROW + (msel & 1) * 8;

    float acc[4][4][4];
    #pragma unroll
    for (int a = 0; a < 4; ++a)
        #pragma unroll
        for (int b = 0; b < 4; ++b)
            #pragma unroll
            for (int c = 0; c < 4; ++c) acc[a][b][c] = 0.f;

    const int KC = CH * 16;
    const int G  = CH * 2;
    const int nchunk = K / KC;

    auto stage = [&](int c, int b) {
        const int ko = c * KC;
        const int TOT = NP * 2 * 128 * G;
        #pragma unroll
        for (int i = 0; i < TOT / 256; ++i) {
            int s = t + (i << 8);
            int half = s / (NP * 128 * G);
            int rem  = s - half * (NP * 128 * G);
            int pl = rem / (128 * G);
            int idx = rem - pl * (128 * G);
            int r = idx / G, gg = idx - (idx / G) * G;
            const bf16* src = half
                ? Bp + (long long)pl * Bs + (long long)(bn + r) * ldb + ko + gg * 8
                : Ap + (long long)pl * As + (long long)(bm + r) * lda + ko + gg * 8;
            uint32_t dst = (half ? sB : sA) + (uint32_t)((b * NP + pl) * TILEB + (r * TROW + gg * 8) * 2);
            asm volatile("cp.async.cg.shared.global [%0], [%1], 16;"
                         :: "r"(dst), "l"((const void*)src));
        }
        asm volatile("cp.async.commit_group;" ::: "memory");
    };

    // self-attention scores: fully-masked output tile -> epilogue with acc=0 (softmax-identical)
    const bool skipmain = (EPI == 8) && (bn + 128 <= bm);
    // self-attention PV: A-chunks with ko+KC <= bm are exact zeros -> skip (bitwise identical)
    int c_start = 0;
    if (EPI == 6 && causal) c_start = bm / KC;

    if (!skipmain) {
        stage(c_start, c_start & 1);
        const int NPROD = (NP == 2) ? 3 : 1;
        const int pa[3] = {0, 0, 1}, pb[3] = {0, 1, 0};

        for (int c = c_start; c < nchunk; ++c) {
            const int b = c & 1;
            __syncthreads();
            if (c + 1 < nchunk) {
                stage(c + 1, b ^ 1);
                asm volatile("cp.async.wait_group 1;" ::: "memory");
            } else {
                asm volatile("cp.async.wait_group 0;" ::: "memory");
            }
            __syncthreads();

            #pragma unroll
            for (int p = 0; p < NPROD; ++p) {
                uint32_t ab = sA + (uint32_t)((b * NP + pa[p]) * TILEB);
                uint32_t bb = sB + (uint32_t)((b * NP + pb[p]) * TILEB);
                #pragma unroll
                for (int kh = 0; kh < CH; ++kh) {
                    uint32_t af[4][4], bfr[4][2];
                    #pragma unroll
                    for (int mt = 0; mt < 4; ++mt) {
                        uint32_t addr = ab + (uint32_t)(((wm + mt * 16) * TROW + kh * 16 + aoff) * 2);
                        asm volatile("ldmatrix.sync.aligned.m8n8.x4.shared.b16 {%0,%1,%2,%3}, [%4];"
                            : "=r"(af[mt][0]), "=r"(af[mt][1]), "=r"(af[mt][2]), "=r"(af[mt][3])
                            : "r"(addr));
                    }
                    #pragma unroll
                    for (int ntp = 0; ntp < 2; ++ntp) {
                        uint32_t addr = bb + (uint32_t)(((wn + ntp * 16) * TROW + kh * 16 + boff) * 2);
                        asm volatile("ldmatrix.sync.aligned.m8n8.x4.shared.b16 {%0,%1,%2,%3}, [%4];"
                            : "=r"(bfr[2 * ntp][0]), "=r"(bfr[2 * ntp][1]),
                              "=r"(bfr[2 * ntp + 1][0]), "=r"(bfr[2 * ntp + 1][1])
                            : "r"(addr));
                    }
                    #pragma unroll
                    for (int mt = 0; mt < 4; ++mt)
                        #pragma unroll
                        for (int nt = 0; nt < 4; ++nt)
                            asm volatile(
                                "mma.sync.aligned.m16n8k16.row.col.f32.bf16.bf16.f32 "
                                "{%0,%1,%2,%3}, {%4,%5,%6,%7}, {%8,%9}, {%0,%1,%2,%3};"
                                : "+f"(acc[mt][nt][0]), "+f"(acc[mt][nt][1]),
                                  "+f"(acc[mt][nt][2]), "+f"(acc[mt][nt][3])
                                : "r"(af[mt][0]), "r"(af[mt][1]), "r"(af[mt][2]), "r"(af[mt][3]),
                                  "r"(bfr[nt][0]), "r"(bfr[nt][1]));
                }
            }
        }
    }

    const int padbase = bo * 512;
    #pragma unroll
    for (int mt = 0; mt < 4; ++mt) {
        int r0 = bm + wm + mt * 16 + g;
        #pragma unroll
        for (int nt = 0; nt < 4; ++nt) {
            int c0 = bn + wn + nt * 8 + t4 * 2;
            float v0 = acc[mt][nt][0], v1 = acc[mt][nt][1];
            float v2 = acc[mt][nt][2], v3 = acc[mt][nt][3];
            if (EPI == 1 || EPI == 2 || EPI == 5 || EPI == 7) {
                float b0 = bias[c0], b1 = bias[c0 + 1];
                v0 += b0; v1 += b1; v2 += b0; v3 += b1;
            }
            if (EPI == 2) {
                v0 = fmaxf(v0, 0.f); v1 = fmaxf(v1, 0.f);
                v2 = fmaxf(v2, 0.f); v3 = fmaxf(v3, 0.f);
            }
            if (EPI == 8 || EPI == 9) {
                v0 = __fdiv_rn(v0, alpha); v1 = __fdiv_rn(v1, alpha);
                v2 = __fdiv_rn(v2, alpha); v3 = __fdiv_rn(v3, alpha);
                if (EPI == 8) {
                    if (c0 < r0)         v0 += NEGB;
                    if (c0 + 1 < r0)     v1 += NEGB;
                    if (c0 < r0 + 8)     v2 += NEGB;
                    if (c0 + 1 < r0 + 8) v3 += NEGB;
                }
                float b0 = bias[padbase + c0], b1 = bias[padbase + c0 + 1];
                v0 += b0; v1 += b1; v2 += b0; v3 += b1;
            }
            if (EPI == 1 || EPI == 8 || EPI == 9) {
                *(float2*)&Cf[(long long)r0 * ldc + c0]       = make_float2(v0, v1);
                *(float2*)&Cf[(long long)(r0 + 8) * ldc + c0] = make_float2(v2, v3);
            } else if (EPI == 10) {
                bf162 q0; q0.x = __float2bfloat16(v0); q0.y = __float2bfloat16(v1);
                bf162 q1; q1.x = __float2bfloat16(v2); q1.y = __float2bfloat16(v3);
                *(bf162*)&Cb[(long long)r0 * ldc + c0]       = q0;
                *(bf162*)&Cb[(long long)(r0 + 8) * ldc + c0] = q1;
            } else if (EPI == 7 && c0 >= vbase) {
                int col = c0 - vbase;
                int hh = col / 96, nn = col - hh * 96;
                int bb2 = r0 >> 9, tk = r0 & 511;
                long long base = (long long)(bb2 * 8 + hh) * 65536 + (long long)nn * 512 + tk;
                bf16 x0 = __float2bfloat16(v0);
                Vt[base]           = x0; Vt[NVT + base]           = __float2bfloat16(v0 - __bfloat162float(x0));
                bf16 x1 = __float2bfloat16(v1);
                Vt[base + 512]     = x1; Vt[NVT + base + 512]     = __float2bfloat16(v1 - __bfloat162float(x1));
                bf16 x2 = __float2bfloat16(v2);
                Vt[base + 8]       = x2; Vt[NVT + base + 8]       = __float2bfloat16(v2 - __bfloat162float(x2));
                bf16 x3 = __float2bfloat16(v3);
                Vt[base + 512 + 8] = x3; Vt[NVT + base + 512 + 8] = __float2bfloat16(v3 - __bfloat162float(x3));
            } else {
                if (EPI != 6 || c0 < Nreal) {
                    splitWr(Cb, Cs, (long long)r0 * ldc + c0, v0, v1);
                    splitWr(Cb, Cs, (long long)(r0 + 8) * ldc + c0, v2, v3);
                }
            }
        }
    }
}

// ------------- fp32 -> 2 bf16 planes (explicit plane stride) -------------
__global__ __launch_bounds__(256) void split2_k(const float* __restrict__ x,
                                                bf16* __restrict__ p, long long n, long long stride) {
    long long i = (long long)blockIdx.x * 256 + threadIdx.x;
    if (i >= n) return;
    float v = x[i];
    bf16 h0 = __float2bfloat16(v);
    p[i] = h0;
    p[stride + i] = __float2bfloat16(v - __bfloat162float(h0));
}

// ------------- coarse top-16 candidate set (bf16 dots) -------------
__global__ __launch_bounds__(256) void topk16_k() {
    int n = blockIdx.x;
    const bf16* drow = g_dotb + (long long)n * KCB;
    float zs = g_zsq[n];
    int t = threadIdx.x;
    float v[32];
    #pragma unroll
    for (int j = 0; j < 32; ++j) {
        int k = j * 256 + t;
        v[j] = (zs + g_cn[k]) - 2.0f * __bfloat162float(drow[k]);
    }
    __shared__ float sv[8]; __shared__ int si[8]; __shared__ int sbi;
    const float INF = __int_as_float(0x7f800000);
    for (int r = 0; r < 16; ++r) {
        float lv = INF; int li = 0x7fffffff;
        #pragma unroll
        for (int j = 0; j < 32; ++j) {
            int k = j * 256 + t;
            if (v[j] < lv) { lv = v[j]; li = k; }
        }
        #pragma unroll
        for (int o = 16; o; o >>= 1) {
            float ov = __shfl_xor_sync(0xffffffffu, lv, o);
            int   oi = __shfl_xor_sync(0xffffffffu, li, o);
            if (ov < lv || (ov == lv && oi < li)) { lv = ov; li = oi; }
        }
        if ((t & 31) == 0) { sv[t >> 5] = lv; si[t >> 5] = li; }
        __syncthreads();
        if (t == 0) {
            float bv = sv[0]; int bi2 = si[0];
            #pragma unroll
            for (int w = 1; w < 8; ++w)
                if (sv[w] < bv || (sv[w] == bv && si[w] < bi2)) { bv = sv[w]; bi2 = si[w]; }
            g_ci[n * 16 + r] = bi2;
            sbi = bi2;
        }
        __syncthreads();
        int bi2 = sbi;
        if ((bi2 & 255) == t) v[bi2 >> 8] = INF;
        __syncthreads();
    }
}

// ------------- exact fp32 rerank of 16 candidates -> top-10 -------------
__global__ __launch_bounds__(256) void rerank_k(const float* __restrict__ cb) {
    int n = blockIdx.x;
    int t = threadIdx.x, w = t >> 5, lane = t & 31;
    __shared__ float sd[16]; __shared__ int sk[16];
    for (int c = w; c < 16; c += 8) {
        int k = g_ci[n * 16 + c];
        const float* zr = g_ze + (long long)n * 768;
        const float* cr = cb + (long long)k * 768;
        float dot = 0.f;
        for (int i = lane * 4; i < 768; i += 128) {
            float4 a = *(const float4*)&zr[i];
            float4 b = *(const float4*)&cr[i];
            dot = fmaf(a.x, b.x, dot); dot = fmaf(a.y, b.y, dot);
            dot = fmaf(a.z, b.z, dot); dot = fmaf(a.w, b.w, dot);
        }
        #pragma unroll
        for (int o = 16; o; o >>= 1) dot += __shfl_xor_sync(0xffffffffu, dot, o);
        if (lane == 0) {
            sd[c] = __fsub_rn(__fadd_rn(g_zsq[n], g_cn[k]), __fmul_rn(2.0f, dot));
            sk[c] = k;
        }
    }
    __syncthreads();
    if (t == 0) {
        bool used[16];
        #pragma unroll
        for (int i = 0; i < 16; ++i) used[i] = false;
        for (int r = 0; r < 10; ++r) {
            float bd = __int_as_float(0x7f800000); int bk = 0x7fffffff, bc = 0;
            #pragma unroll
            for (int c = 0; c < 16; ++c)
                if (!used[c] && (sd[c] < bd || (sd[c] == bd && sk[c] < bk))) {
                    bd = sd[c]; bk = sk[c]; bc = c;
                }
            used[bc] = true;
            g_topd[n * 10 + r] = -bd;
            g_topi[n * 10 + r] = bk;
        }
    }
}

// ------------- threefry + gumbel sample -------------
__device__ __forceinline__ unsigned rotl32(unsigned x, int r) { return (x << r) | (x >> (32 - r)); }
__device__ __forceinline__ void tf4(unsigned& x0, unsigned& x1, int r0, int r1, int r2, int r3) {
    x0 += x1; x1 = rotl32(x1, r0); x1 ^= x0;
    x0 += x1; x1 = rotl32(x1, r1); x1 ^= x0;
    x0 += x1; x1 = rotl32(x1, r2); x1 ^= x0;
    x0 += x1; x1 = rotl32(x1, r3); x1 ^= x0;
}
__device__ __forceinline__ void threefry(unsigned c0, unsigned c1, unsigned& o0, unsigned& o1) {
    const unsigned k0 = 0u, k1 = 42u, k2 = 0x1BD11BDAu ^ 0u ^ 42u;
    unsigned x0 = c0 + k0, x1 = c1 + k1;
    tf4(x0, x1, 13, 15, 26, 6);  x0 += k1; x1 += k2 + 1u;
    tf4(x0, x1, 17, 29, 16, 24); x0 += k2; x1 += k0 + 2u;
    tf4(x0, x1, 13, 15, 26, 6);  x0 += k0; x1 += k1 + 3u;
    tf4(x0, x1, 17, 29, 16, 24); x0 += k1; x1 += k2 + 4u;
    tf4(x0, x1, 13, 15, 26, 6);  x0 += k2; x1 += k0 + 5u;
    o0 = x0; o1 = x1;
}
__global__ __launch_bounds__(256) void sample_k() {
    int n = blockIdx.x * 256 + threadIdx.x;
    float best = -__int_as_float(0x7f800000); int bj = 0;
    #pragma unroll
    for (int j = 0; j < 10; ++j) {
        unsigned m = (unsigned)n * 10u + (unsigned)j, o0, o1;
        threefry(0u, m, o0, o1);
        unsigned bits = o0 ^ o1;
        float f = __uint_as_float((bits >> 9) | 0x3f800000u) - 1.0f;
        float u = fmaxf(1e-10f, __fadd_rn(f, 1e-10f));
        float gum = -logf(-logf(u));
        float val = __fadd_rn(g_topd[n * 10 + j], gum);
        if (val > best) { best = val; bj = j; }
    }
    g_enc[n] = g_topi[n * 10 + bj];
}

// ------------- quantize (+fused split of h) -------------
__global__ __launch_bounds__(256) void quant_k(const float* __restrict__ cb) {
    int n = blockIdx.x;
    long long idx = g_enc[n];
    #pragma unroll
    for (int i = 0; i < 3; ++i) {
        int d = threadIdx.x + i * 256;
        long long o = (long long)n * 768 + d;
        float z = g_ze[o];
        float q = cb[idx * 768 + d];
        float hv = __fadd_rn(z, __fsub_rn(q, z));
        g_h[o] = hv;
        bf16 h0 = __float2bfloat16(hv);
        g_hsp[o] = h0;
        g_hsp[NA + o] = __float2bfloat16(hv - __bfloat162float(h0));
    }
}

// ------------- warp-per-row softmax: fp32 scores -> prob planes -------------
__global__ __launch_bounds__(256) void softmax_k() {
    long long r = (long long)blockIdx.x * 8 + (threadIdx.x >> 5);
    const int lane = threadIdx.x & 31;
    const float* row = g_scores + r * 512;
    float v[16];
    float m = -__int_as_float(0x7f800000);
    #pragma unroll
    for (int j = 0; j < 16; ++j) { v[j] = row[j * 32 + lane]; m = fmaxf(m, v[j]); }
    #pragma unroll
    for (int o = 16; o; o >>= 1) m = fmaxf(m, __shfl_xor_sync(0xffffffffu, m, o));
    float s = 0.f;
    #pragma unroll
    for (int j = 0; j < 16; ++j) { v[j] = __expf(v[j] - m); s += v[j]; }
    #pragma unroll
    for (int o = 16; o; o >>= 1) s += __shfl_xor_sync(0xffffffffu, s, o);
    #pragma unroll
    for (int j = 0; j < 16; ++j) {
        float p = __fdiv_rn(v[j], s);
        long long o2 = r * 512 + j * 32 + lane;
        bf16 a0 = __float2bfloat16(p);
        g_psp[o2] = a0;
        g_psp[NP_ + o2] = __float2bfloat16(p - __bfloat162float(a0));
    }
}

// ------------- residual + LayerNorm (+fused split of h) -------------
__global__ __launch_bounds__(256) void addln_k(float* __restrict__ h, const float* __restrict__ res,
                                               const float* __restrict__ g, const float* __restrict__ b) {
    int n = blockIdx.x;
    __shared__ float red[8];
    float v[3]; float s = 0.f;
    #pragma unroll
    for (int i = 0; i < 3; ++i) {
        int d = threadIdx.x + i * 256;
        v[i] = h[(long long)n * 768 + d] + res[(long long)n * 768 + d];
        s += v[i];
    }
    s = blkSum(s, red);
    float mean = s * (1.0f / 768.0f);
    float vs = 0.f;
    #pragma unroll
    for (int i = 0; i < 3; ++i) { float d0 = v[i] - mean; vs += d0 * d0; }
    vs = blkSum(vs, red);
    float inv = __fdiv_rn(1.0f, sqrtf(vs * (1.0f / 768.0f) + 1e-5f));
    #pragma unroll
    for (int i = 0; i < 3; ++i) {
        int d = threadIdx.x + i * 256;
        long long o = (long long)n * 768 + d;
        float hv = (v[i] - mean) * inv * g[d] + b[d];
        h[o] = hv;
        bf16 h0 = __float2bfloat16(hv);
        g_hsp[o] = h0;
        g_hsp[NA + o] = __float2bfloat16(hv - __bfloat162float(h0));
    }
}

// ------------- host side -------------
struct HArgs {
    int M, N, K;
    const bf16 *A; int lda; long long As, sA1, sA2;
    const bf16 *B; int ldb; long long Bs, sB1, sB2;
    float* Cf; bf16* Cb; int ldc; long long Cs, sC1, sC2;
    cfp bias; float alpha; int Z, bdiv, Nreal;
    bf16* Vt; int vbase; int causal;
};
static void hgemm(int np, int epi, const HArgs& a) {
    dim3 g(a.N / 128, a.M / 128, a.Z);
    size_t sm = (size_t)np * 4 * TILEB;
    int ch = (a.K % 48 == 0) ? 3 : 2;
#define HG(NPV,EV,CV) hgemm_k<NPV,EV,CV><<<g,256,sm>>>(a.M,a.N,a.K,a.A,a.lda,a.As,a.sA1,a.sA2, \
    a.B,a.ldb,a.Bs,a.sB1,a.sB2,a.Cf,a.Cb,a.ldc,a.Cs,a.sC1,a.sC2,a.bias,a.alpha,a.bdiv,a.Nreal,a.Vt,a.vbase,a.causal)
    if (np == 1) { HG(1,10,3); return; }
    if (ch == 3) {
        switch (epi) {
            case 1: HG(2,1,3); break;  case 2: HG(2,2,3); break;
            case 5: HG(2,5,3); break;  case 7: HG(2,7,3); break;
            case 8: HG(2,8,3); break;  case 9: HG(2,9,3); break;
            default: HG(2,1,3); break;
        }
    } else {
        switch (epi) {
            case 6: HG(2,6,2); break;
            default: HG(2,1,2); break;
        }
    }
#undef HG
}
static void split2(cfp x, bf16* p, long long n, long long stride) {
    split2_k<<<(unsigned)((n + 255) / 256), 256>>>(x, p, n, stride);
}

extern "C" void kernel_launch(void* const* d_in, const int* in_sizes, int n_in,
                              void* d_out, int out_size) {
    cfp x     = (cfp)d_in[0];
    cfp cb    = (cfp)d_in[1];
    cfp sa_in_w = (cfp)d_in[2],  sa_in_b = (cfp)d_in[3];
    cfp sa_out_w= (cfp)d_in[4],  sa_out_b= (cfp)d_in[5];
    cfp ca_in_w = (cfp)d_in[6],  ca_in_b = (cfp)d_in[7];
    cfp ca_out_w= (cfp)d_in[8],  ca_out_b= (cfp)d_in[9];
    cfp ln1_g = (cfp)d_in[10], ln1_b = (cfp)d_in[11];
    cfp ln2_g = (cfp)d_in[12], ln2_b = (cfp)d_in[13];
    cfp ln3_g = (cfp)d_in[14], ln3_b = (cfp)d_in[15];
    cfp ff_w1 = (cfp)d_in[16], ff_b1 = (cfp)d_in[17];
    cfp ff_w2 = (cfp)d_in[18], ff_b2 = (cfp)d_in[19];
    cfp out_w = (cfp)d_in[20], out_b = (cfp)d_in[21];
    float* out = (float*)d_out;

    cudaFuncSetAttribute(hgemm_k<1,10,3>, cudaFuncAttributeMaxDynamicSharedMemorySize, 4 * TILEB);
    cudaFuncSetAttribute(hgemm_k<2,1,3>, cudaFuncAttributeMaxDynamicSharedMemorySize, 8 * TILEB);
    cudaFuncSetAttribute(hgemm_k<2,2,3>, cudaFuncAttributeMaxDynamicSharedMemorySize, 8 * TILEB);
    cudaFuncSetAttribute(hgemm_k<2,5,3>, cudaFuncAttributeMaxDynamicSharedMemorySize, 8 * TILEB);
    cudaFuncSetAttribute(hgemm_k<2,7,3>, cudaFuncAttributeMaxDynamicSharedMemorySize, 8 * TILEB);
    cudaFuncSetAttribute(hgemm_k<2,8,3>, cudaFuncAttributeMaxDynamicSharedMemorySize, 8 * TILEB);
    cudaFuncSetAttribute(hgemm_k<2,9,3>, cudaFuncAttributeMaxDynamicSharedMemorySize, 8 * TILEB);
    cudaFuncSetAttribute(hgemm_k<2,1,2>, cudaFuncAttributeMaxDynamicSharedMemorySize, 8 * TILEB);
    cudaFuncSetAttribute(hgemm_k<2,6,2>, cudaFuncAttributeMaxDynamicSharedMemorySize, 8 * TILEB);

    float *ze, *h, *proj, *scores, *padb;
    bf16 *dotb, *zsp, *hsp, *atsp, *fsp, *qsp, *cbsp, *psp, *vtsp, *wall;
    cudaGetSymbolAddress((void**)&ze, g_ze);
    cudaGetSymbolAddress((void**)&h, g_h);
    cudaGetSymbolAddress((void**)&proj, g_proj);
    cudaGetSymbolAddress((void**)&scores, g_scores);
    cudaGetSymbolAddress((void**)&padb, g_padbias);
    cudaGetSymbolAddress((void**)&dotb, g_dotb);
    cudaGetSymbolAddress((void**)&zsp, g_zsp);
    cudaGetSymbolAddress((void**)&hsp, g_hsp);
    cudaGetSymbolAddress((void**)&atsp, g_atsp);
    cudaGetSymbolAddress((void**)&fsp, g_fsp);
    cudaGetSymbolAddress((void**)&qsp, g_qsp);
    cudaGetSymbolAddress((void**)&cbsp, g_cbsp);
    cudaGetSymbolAddress((void**)&psp, g_psp);
    cudaGetSymbolAddress((void**)&vtsp, g_vtsp);
    cudaGetSymbolAddress((void**)&wall, g_wall);

    const float sc = sqrtf(96.f);

    // ---- pre-split ALL weights into the wall (plane stride NW) ----
    split2(sa_in_w,  wall + W_SIW, 10616832LL, NW);
    split2(sa_out_w, wall + W_SOW, 3538944LL,  NW);
    split2(ca_in_w,  wall + W_CIW, 10616832LL, NW);
    split2(ca_out_w, wall + W_COW, 3538944LL,  NW);
    split2(ff_w1,    wall + W_W1,  9437184LL,  NW);
    split2(ff_w2,    wall + W_W2,  9437184LL,  NW);
    split2(out_w,    wall + W_OW,  589824LL,   NW);

    // ---- VQ: coarse bf16 (single-plane dots) -> exact rerank ----
    ze_kernel<<<8192, 256>>>(x);
    cn_kernel<<<8192, 256>>>(cb);
    split2(cb, cbsp, NA, NA);
    { HArgs a = {8192, 8192, 768, zsp, 768, NA, 0, 0, cbsp, 768, NA, 0, 0,
                 nullptr, dotb, 8192, 0, 0, 0, nullptr, 1.f, 1, 1, 0, nullptr, 0, 0};
      hgemm(1, 10, a); }
    topk16_k<<<8192, 256>>>();
    rerank_k<<<8192, 256>>>(cb);
    sample_k<<<32, 256>>>();
    quant_k<<<8192, 256>>>(cb);

    for (int l = 0; l < 6; ++l) {
        const bf16* siw = wall + W_SIW + (long long)l * 2304 * 768;
        const bf16* sow = wall + W_SOW + (long long)l * 768 * 768;
        const bf16* ciw = wall + W_CIW + (long long)l * 2304 * 768;
        const bf16* cow = wall + W_COW + (long long)l * 768 * 768;
        const bf16* w1  = wall + W_W1  + (long long)l * 2048 * 768;
        const bf16* w2  = wall + W_W2  + (long long)l * 768 * 2048;
        cfp sib = sa_in_b + l * 2304, sob = sa_out_b + l * 768;
        cfp cib = ca_in_b + l * 2304, cob = ca_out_b + l * 768;
        cfp b1 = ff_b1 + l * 2048, b2 = ff_b2 + l * 768;

        for (int att = 0; att < 2; ++att) {
            // qkv projections -> qsp planes (+ V transposed into vtsp)
            if (att == 0) {
                HArgs a = {8192, 2304, 768, hsp, 768, NA, 0, 0, siw, 768, NW, 0, 0,
                           nullptr, qsp, 2304, NQ, 0, 0, sib, 0.f, 1, 1, 0, vtsp, 1536, 0};
                hgemm(2, 7, a);
            } else {
                HArgs aq = {8192, 768, 768, hsp, 768, NA, 0, 0, ciw, 768, NW, 0, 0,
                            nullptr, qsp, 2304, NQ, 0, 0, cib, 0.f, 1, 1, 0, nullptr, 0, 0};
                hgemm(2, 5, aq);
                HArgs akv = {8192, 1536, 768, zsp, 768, NA, 0, 0, ciw + 768LL * 768, 768, NW, 0, 0,
                             nullptr, qsp + 768, 2304, NQ, 0, 0, cib + 768, 0.f, 1, 1, 0, vtsp, 768, 0};
                hgemm(2, 7, akv);
            }
            // scores = q@k^T / sc + mask  (fp32; EPI8 early-exits masked tiles)
            { HArgs a = {512, 512, 96, qsp, 2304, NQ, 512LL * 2304, 96,
                         qsp + 768, 2304, NQ, 512LL * 2304, 96,
                         scores, nullptr, 512, 0, 8LL * 262144, 262144,
                         padb, sc, 128, 8, 0, nullptr, 0, 0};
              hgemm(2, att == 0 ? 8 : 9, a); }
            softmax_k<<<8192, 256>>>();
            // attn = probs @ v  -> atsp planes (self: skip all-zero prob chunks)
            { HArgs a = {512, 128, 512, psp, 512, NP_, 8LL * 262144, 262144,
                         vtsp, 512, NVT, 8LL * 65536, 65536,
                         nullptr, atsp, 768, NA, 512LL * 768, 96,
                         nullptr, 1.f, 128, 8, 96, nullptr, 0, att == 0 ? 1 : 0};
              hgemm(2, 6, a); }
            // out projection + addln
            { HArgs a = {8192, 768, 768, atsp, 768, NA, 0, 0, att == 0 ? sow : cow, 768, NW, 0, 0,
                         proj, nullptr, 768, 0, 0, 0, att == 0 ? sob : cob, 0.f, 1, 1, 0, nullptr, 0, 0};
              hgemm(2, 1, a); }
            addln_k<<<8192, 256>>>(h, proj,
                (att == 0 ? ln1_g : ln2_g) + l * 768, (att == 0 ? ln1_b : ln2_b) + l * 768);
        }

        // ---- feed-forward ----
        { HArgs a = {8192, 2048, 768, hsp, 768, NA, 0, 0, w1, 768, NW, 0, 0,
                     nullptr, fsp, 2048, NF, 0, 0, b1, 0.f, 1, 1, 0, nullptr, 0, 0};
          hgemm(2, 2, a); }
        { HArgs a = {8192, 768, 2048, fsp, 2048, NF, 0, 0, w2, 2048, NW, 0, 0,
                     proj, nullptr, 768, 0, 0, 0, b2, 0.f, 1, 1, 0, nullptr, 0, 0};
          hgemm(2, 1, a); }
        addln_k<<<8192, 256>>>(h, proj, ln3_g + l * 768, ln3_b + l * 768);
    }

    // ---- output projection ----
    { HArgs a = {8192, 768, 768, hsp, 768, NA, 0, 0, wall + W_OW, 768, NW, 0, 0,
                 out, nullptr, 768, 0, 0, 0, out_b, 0.f, 1, 1, 0, nullptr, 0, 0};
      hgemm(2, 1, a); }
}

// round 17
// speedup vs baseline: 1.5723x; 1.5235x over previous
#include <cuda_runtime.h>
#include <cuda_fp16.h>
#include <stdint.h>
#include <math.h>

#define NTOK 8192
#define KCB  8192
#define NEGB (-1e9f)

typedef const float* cfp;

// plane strides
#define NA  (8192LL*768)
#define NF  (8192LL*2048)
#define NQ  (8192LL*2304)
#define NP_ (33554432LL)          // prob plane: 128*512*512
#define NVT (8388608LL)           // vT plane: 128*128*512

// pre-split weight wall: offsets (elems) and total
#define W_SIW 0LL
#define W_SOW 10616832LL
#define W_CIW 14155776LL
#define W_COW 24772608LL
#define W_W1  28311552LL
#define W_W2  37748736LL
#define W_OW  47185920LL
#define NW    47775744LL

// smem tile: 128 rows x 56 elems (112B stride, conflict-free for ldmatrix)
#define TROW 56
#define TILEB (128*TROW*2)        // 14336 bytes

// ------------- static device scratch -------------
static __device__ float g_ze[NTOK*768];
static __device__ float g_h[NTOK*768];
static __device__ float g_proj[NTOK*768];
static __device__ float g_scores[128*512*512];
static __device__ float g_cn[KCB];
static __device__ float g_zsq[NTOK];
static __device__ float g_padbias[NTOK];
static __device__ float g_topd[NTOK*10];
static __device__ int   g_topi[NTOK*10];
static __device__ int   g_enc[NTOK];
static __device__ int   g_ci[NTOK*16];
// fp16 buffers: activations single-plane, weights/V split-2
static __device__ __align__(16) __half g_dotb[(long long)NTOK*KCB];
static __device__ __align__(16) __half g_zsp[NA];
static __device__ __align__(16) __half g_hsp[NA];
static __device__ __align__(16) __half g_atsp[NA];
static __device__ __align__(16) __half g_fsp[NF];
static __device__ __align__(16) __half g_qsp[NQ];
static __device__ __align__(16) __half g_cbsp[NA];
static __device__ __align__(16) __half g_psp[NP_];
static __device__ __align__(16) __half g_vtsp[2*NVT];   // split-2; rows n>=96 stay zero
static __device__ __align__(16) __half g_wall[2*NW];    // split-2 weights

// ------------- helpers -------------
__device__ __forceinline__ float blkSum(float v, float* red) {
    #pragma unroll
    for (int o = 16; o; o >>= 1) v += __shfl_xor_sync(0xffffffffu, v, o);
    if ((threadIdx.x & 31) == 0) red[threadIdx.x >> 5] = v;
    __syncthreads();
    float s = red[0];
    #pragma unroll
    for (int i = 1; i < 8; ++i) s += red[i];
    __syncthreads();
    return s;
}
__device__ __forceinline__ uint32_t s2u(const void* p) {
    uint32_t a;
    asm("{ .reg .u64 t; cvta.to.shared.u64 t, %1; cvt.u32.u64 %0, t; }" : "=r"(a) : "l"(p));
    return a;
}

// ------------- z_e, pad, |z|^2 (+fused fp16 shadow) -------------
__global__ __launch_bounds__(256) void ze_kernel(const float* __restrict__ x) {
    int n = blockIdx.x;
    __shared__ float red[8];
    float v[3]; float ss = 0.f;
    #pragma unroll
    for (int i = 0; i < 3; ++i) {
        int d = threadIdx.x + i * 256;
        v[i] = x[(long long)n * 768 + d];
        ss += v[i] * v[i];
    }
    ss = blkSum(ss, red);
    bool pad = (sqrtf(ss) <= 1e-6f);
    #pragma unroll
    for (int i = 0; i < 3; ++i) {
        int d = threadIdx.x + i * 256;
        float z = pad ? 0.f : v[i];
        long long o = (long long)n * 768 + d;
        g_ze[o] = z;
        g_zsp[o] = __float2half(z);
    }
    if (threadIdx.x == 0) { g_padbias[n] = pad ? NEGB : 0.f; g_zsq[n] = pad ? 0.f : ss; }
}

__global__ __launch_bounds__(256) void cn_kernel(const float* __restrict__ cb) {
    int k = blockIdx.x;
    __shared__ float red[8];
    float ss = 0.f;
    #pragma unroll
    for (int i = 0; i < 3; ++i) {
        int d = threadIdx.x + i * 256;
        float c = cb[(long long)k * 768 + d];
        ss += c * c;
    }
    ss = blkSum(ss, red);
    if (threadIdx.x == 0) g_cn[k] = ss;
}

// ------------- fp16 HMMA GEMM: A single plane, B NPB planes -------------
// C = A@B^T (+epilogue). A[M,K] lda; B[N,K] ldb with NPB fp16 planes (stride Bs).
// EPI 1: fp32 acc+bias     2: half relu(acc+bias)   5: half acc+bias
//     6: half acc, cols < Nreal only (causal=1: skip all-zero A chunks)
//     7: half acc+bias for cols < vbase; split-2 V-transpose into Vt for cols >= vbase
//     8: fp32 acc/alpha + causal + padbias (fully-masked tiles early-exit)
//     9: fp32 acc/alpha + padbias
//    10: half acc (coarse VQ dots)
template<int NPB, int EPI, int CH>
__global__ __launch_bounds__(256)
void hgemm_k(int M, int N, int K,
             const __half* __restrict__ Ap, int lda, long long sA1, long long sA2,
             const __half* __restrict__ Bp, int ldb, long long Bs, long long sB1, long long sB2,
             float* __restrict__ Cf, __half* __restrict__ Cb, int ldc,
             long long sC1, long long sC2,
             const float* __restrict__ bias, float alpha, int bdiv, int Nreal,
             __half* __restrict__ Vt, int vbase, int causal)
{
    extern __shared__ __align__(1024) char hsm[];
    const int bz = blockIdx.z;
    const int bo = bz / bdiv, bi = bz % bdiv;
    Ap += bo * sA1 + bi * sA2;
    Bp += bo * sB1 + bi * sB2;
    if (EPI == 1 || EPI == 8 || EPI == 9) Cf += bo * sC1 + bi * sC2;
    else Cb += bo * sC1 + bi * sC2;

    uint32_t sA = s2u(hsm);
    uint32_t sB = sA + 2 * TILEB;
    const int t = threadIdx.x, lane = t & 31, warp = t >> 5;
    const int g = lane >> 2, t4 = lane & 3;
    const int bm = blockIdx.y * 128, bn = blockIdx.x * 128;
    const int wm = (warp >> 2) * 64, wn = (warp & 3) * 32;

    const int lane7 = lane & 7, msel = lane >> 3;
    const int aoff = (lane7 + (msel & 1) * 8) * TROW + (msel >> 1) * 8;
    const int boff = (lane7 + (msel >> 1) * 8) * TROW + (msel & 1) * 8;

    float acc[4][4][4];
    #pragma unroll
    for (int a = 0; a < 4; ++a)
        #pragma unroll
        for (int b = 0; b < 4; ++b)
            #pragma unroll
            for (int c = 0; c < 4; ++c) acc[a][b][c] = 0.f;

    const int KC = CH * 16;
    const int G  = CH * 2;
    const int AG = 128 * G;
    const int nchunk = K / KC;

    auto stage = [&](int c, int b) {
        const int ko = c * KC;
        const int TOT = (1 + NPB) * AG;
        #pragma unroll
        for (int i = 0; i < TOT / 256; ++i) {
            int s = t + (i << 8);
            const __half* src; uint32_t dst;
            if (s < AG) {
                int r = s / G, gg = s - (s / G) * G;
                src = Ap + (long long)(bm + r) * lda + ko + gg * 8;
                dst = sA + (uint32_t)(b * TILEB + (r * TROW + gg * 8) * 2);
            } else {
                int s2 = s - AG;
                int pl = s2 / AG, idx = s2 - pl * AG;
                int r = idx / G, gg = idx - (idx / G) * G;
                src = Bp + (long long)pl * Bs + (long long)(bn + r) * ldb + ko + gg * 8;
                dst = sB + (uint32_t)((b * NPB + pl) * TILEB + (r * TROW + gg * 8) * 2);
            }
            asm volatile("cp.async.cg.shared.global [%0], [%1], 16;"
                         :: "r"(dst), "l"((const void*)src));
        }
        asm volatile("cp.async.commit_group;" ::: "memory");
    };

    // self-attn scores: fully-masked output tile -> epilogue with acc=0 (softmax-identical)
    const bool skipmain = (EPI == 8) && (bn + 128 <= bm);
    // self-attn PV: A-chunks with ko+KC <= bm are exact zeros -> skip (bitwise identical)
    int c_start = 0;
    if (EPI == 6 && causal) c_start = bm / KC;

    if (!skipmain) {
        stage(c_start, c_start & 1);
        for (int c = c_start; c < nchunk; ++c) {
            const int b = c & 1;
            __syncthreads();
            if (c + 1 < nchunk) {
                stage(c + 1, b ^ 1);
                asm volatile("cp.async.wait_group 1;" ::: "memory");
            } else {
                asm volatile("cp.async.wait_group 0;" ::: "memory");
            }
            __syncthreads();

            uint32_t ab = sA + (uint32_t)(b * TILEB);
            #pragma unroll
            for (int kh = 0; kh < CH; ++kh) {
                uint32_t af[4][4];
                #pragma unroll
                for (int mt = 0; mt < 4; ++mt) {
                    uint32_t addr = ab + (uint32_t)(((wm + mt * 16) * TROW + kh * 16 + aoff) * 2);
                    asm volatile("ldmatrix.sync.aligned.m8n8.x4.shared.b16 {%0,%1,%2,%3}, [%4];"
                        : "=r"(af[mt][0]), "=r"(af[mt][1]), "=r"(af[mt][2]), "=r"(af[mt][3])
                        : "r"(addr));
                }
                #pragma unroll
                for (int pb = 0; pb < NPB; ++pb) {
                    uint32_t bb = sB + (uint32_t)((b * NPB + pb) * TILEB);
                    uint32_t bfr[4][2];
                    #pragma unroll
                    for (int ntp = 0; ntp < 2; ++ntp) {
                        uint32_t addr = bb + (uint32_t)(((wn + ntp * 16) * TROW + kh * 16 + boff) * 2);
                        asm volatile("ldmatrix.sync.aligned.m8n8.x4.shared.b16 {%0,%1,%2,%3}, [%4];"
                            : "=r"(bfr[2 * ntp][0]), "=r"(bfr[2 * ntp][1]),
                              "=r"(bfr[2 * ntp + 1][0]), "=r"(bfr[2 * ntp + 1][1])
                            : "r"(addr));
                    }
                    #pragma unroll
                    for (int mt = 0; mt < 4; ++mt)
                        #pragma unroll
                        for (int nt = 0; nt < 4; ++nt)
                            asm volatile(
                                "mma.sync.aligned.m16n8k16.row.col.f32.f16.f16.f32 "
                                "{%0,%1,%2,%3}, {%4,%5,%6,%7}, {%8,%9}, {%0,%1,%2,%3};"
                                : "+f"(acc[mt][nt][0]), "+f"(acc[mt][nt][1]),
                                  "+f"(acc[mt][nt][2]), "+f"(acc[mt][nt][3])
                                : "r"(af[mt][0]), "r"(af[mt][1]), "r"(af[mt][2]), "r"(af[mt][3]),
                                  "r"(bfr[nt][0]), "r"(bfr[nt][1]));
                }
            }
        }
    }

    const int padbase = bo * 512;
    #pragma unroll
    for (int mt = 0; mt < 4; ++mt) {
        int r0 = bm + wm + mt * 16 + g;
        #pragma unroll
        for (int nt = 0; nt < 4; ++nt) {
            int c0 = bn + wn + nt * 8 + t4 * 2;
            float v0 = acc[mt][nt][0], v1 = acc[mt][nt][1];
            float v2 = acc[mt][nt][2], v3 = acc[mt][nt][3];
            if (EPI == 1 || EPI == 2 || EPI == 5 || EPI == 7) {
                float b0 = bias[c0], b1 = bias[c0 + 1];
                v0 += b0; v1 += b1; v2 += b0; v3 += b1;
            }
            if (EPI == 2) {
                v0 = fmaxf(v0, 0.f); v1 = fmaxf(v1, 0.f);
                v2 = fmaxf(v2, 0.f); v3 = fmaxf(v3, 0.f);
            }
            if (EPI == 8 || EPI == 9) {
                v0 = __fdiv_rn(v0, alpha); v1 = __fdiv_rn(v1, alpha);
                v2 = __fdiv_rn(v2, alpha); v3 = __fdiv_rn(v3, alpha);
                if (EPI == 8) {
                    if (c0 < r0)         v0 += NEGB;
                    if (c0 + 1 < r0)     v1 += NEGB;
                    if (c0 < r0 + 8)     v2 += NEGB;
                    if (c0 + 1 < r0 + 8) v3 += NEGB;
                }
                float b0 = bias[padbase + c0], b1 = bias[padbase + c0 + 1];
                v0 += b0; v1 += b1; v2 += b0; v3 += b1;
            }
            if (EPI == 1 || EPI == 8 || EPI == 9) {
                *(float2*)&Cf[(long long)r0 * ldc + c0]       = make_float2(v0, v1);
                *(float2*)&Cf[(long long)(r0 + 8) * ldc + c0] = make_float2(v2, v3);
            } else if (EPI == 7 && c0 >= vbase) {
                int col = c0 - vbase;
                int hh = col / 96, nn = col - hh * 96;
                int bb2 = r0 >> 9, tk = r0 & 511;
                long long base = (long long)(bb2 * 8 + hh) * 65536 + (long long)nn * 512 + tk;
                __half x0 = __float2half(v0);
                Vt[base]           = x0; Vt[NVT + base]           = __float2half(v0 - __half2float(x0));
                __half x1 = __float2half(v1);
                Vt[base + 512]     = x1; Vt[NVT + base + 512]     = __float2half(v1 - __half2float(x1));
                __half x2 = __float2half(v2);
                Vt[base + 8]       = x2; Vt[NVT + base + 8]       = __float2half(v2 - __half2float(x2));
                __half x3 = __float2half(v3);
                Vt[base + 512 + 8] = x3; Vt[NVT + base + 512 + 8] = __float2half(v3 - __half2float(x3));
            } else {
                if (EPI != 6 || c0 < Nreal) {
                    __half2 q0; q0.x = __float2half(v0); q0.y = __float2half(v1);
                    __half2 q1; q1.x = __float2half(v2); q1.y = __float2half(v3);
                    *(__half2*)&Cb[(long long)r0 * ldc + c0]       = q0;
                    *(__half2*)&Cb[(long long)(r0 + 8) * ldc + c0] = q1;
                }
            }
        }
    }
}

// ------------- fp32 -> 2 fp16 planes (weights) -------------
__global__ __launch_bounds__(256) void splitw_k(const float* __restrict__ x,
                                                __half* __restrict__ p, long long n, long long stride) {
    long long i = (long long)blockIdx.x * 256 + threadIdx.x;
    if (i >= n) return;
    float v = x[i];
    __half h0 = __float2half(v);
    p[i] = h0;
    p[stride + i] = __float2half(v - __half2float(h0));
}
// ------------- fp32 -> single fp16 plane -------------
__global__ __launch_bounds__(256) void tohalf_k(const float* __restrict__ x,
                                                __half* __restrict__ p, long long n) {
    long long i = (long long)blockIdx.x * 256 + threadIdx.x;
    if (i >= n) return;
    p[i] = __float2half(x[i]);
}

// ------------- coarse top-16 candidate set (fp16 dots) -------------
__global__ __launch_bounds__(256) void topk16_k() {
    int n = blockIdx.x;
    const __half* drow = g_dotb + (long long)n * KCB;
    float zs = g_zsq[n];
    int t = threadIdx.x;
    float v[32];
    #pragma unroll
    for (int j = 0; j < 32; ++j) {
        int k = j * 256 + t;
        v[j] = (zs + g_cn[k]) - 2.0f * __half2float(drow[k]);
    }
    __shared__ float sv[8]; __shared__ int si[8]; __shared__ int sbi;
    const float INF = __int_as_float(0x7f800000);
    for (int r = 0; r < 16; ++r) {
        float lv = INF; int li = 0x7fffffff;
        #pragma unroll
        for (int j = 0; j < 32; ++j) {
            int k = j * 256 + t;
            if (v[j] < lv) { lv = v[j]; li = k; }
        }
        #pragma unroll
        for (int o = 16; o; o >>= 1) {
            float ov = __shfl_xor_sync(0xffffffffu, lv, o);
            int   oi = __shfl_xor_sync(0xffffffffu, li, o);
            if (ov < lv || (ov == lv && oi < li)) { lv = ov; li = oi; }
        }
        if ((t & 31) == 0) { sv[t >> 5] = lv; si[t >> 5] = li; }
        __syncthreads();
        if (t == 0) {
            float bv = sv[0]; int bi2 = si[0];
            #pragma unroll
            for (int w = 1; w < 8; ++w)
                if (sv[w] < bv || (sv[w] == bv && si[w] < bi2)) { bv = sv[w]; bi2 = si[w]; }
            g_ci[n * 16 + r] = bi2;
            sbi = bi2;
        }
        __syncthreads();
        int bi2 = sbi;
        if ((bi2 & 255) == t) v[bi2 >> 8] = INF;
        __syncthreads();
    }
}

// ------------- exact fp32 rerank of 16 candidates -> top-10 -------------
__global__ __launch_bounds__(256) void rerank_k(const float* __restrict__ cb) {
    int n = blockIdx.x;
    int t = threadIdx.x, w = t >> 5, lane = t & 31;
    __shared__ float sd[16]; __shared__ int sk[16];
    for (int c = w; c < 16; c += 8) {
        int k = g_ci[n * 16 + c];
        const float* zr = g_ze + (long long)n * 768;
        const float* cr = cb + (long long)k * 768;
        float dot = 0.f;
        for (int i = lane * 4; i < 768; i += 128) {
            float4 a = *(const float4*)&zr[i];
            float4 b = *(const float4*)&cr[i];
            dot = fmaf(a.x, b.x, dot); dot = fmaf(a.y, b.y, dot);
            dot = fmaf(a.z, b.z, dot); dot = fmaf(a.w, b.w, dot);
        }
        #pragma unroll
        for (int o = 16; o; o >>= 1) dot += __shfl_xor_sync(0xffffffffu, dot, o);
        if (lane == 0) {
            sd[c] = __fsub_rn(__fadd_rn(g_zsq[n], g_cn[k]), __fmul_rn(2.0f, dot));
            sk[c] = k;
        }
    }
    __syncthreads();
    if (t == 0) {
        bool used[16];
        #pragma unroll
        for (int i = 0; i < 16; ++i) used[i] = false;
        for (int r = 0; r < 10; ++r) {
            float bd = __int_as_float(0x7f800000); int bk = 0x7fffffff, bc = 0;
            #pragma unroll
            for (int c = 0; c < 16; ++c)
                if (!used[c] && (sd[c] < bd || (sd[c] == bd && sk[c] < bk))) {
                    bd = sd[c]; bk = sk[c]; bc = c;
                }
            used[bc] = true;
            g_topd[n * 10 + r] = -bd;
            g_topi[n * 10 + r] = bk;
        }
    }
}

// ------------- threefry + gumbel sample -------------
__device__ __forceinline__ unsigned rotl32(unsigned x, int r) { return (x << r) | (x >> (32 - r)); }
__device__ __forceinline__ void tf4(unsigned& x0, unsigned& x1, int r0, int r1, int r2, int r3) {
    x0 += x1; x1 = rotl32(x1, r0); x1 ^= x0;
    x0 += x1; x1 = rotl32(x1, r1); x1 ^= x0;
    x0 += x1; x1 = rotl32(x1, r2); x1 ^= x0;
    x0 += x1; x1 = rotl32(x1, r3); x1 ^= x0;
}
__device__ __forceinline__ void threefry(unsigned c0, unsigned c1, unsigned& o0, unsigned& o1) {
    const unsigned k0 = 0u, k1 = 42u, k2 = 0x1BD11BDAu ^ 0u ^ 42u;
    unsigned x0 = c0 + k0, x1 = c1 + k1;
    tf4(x0, x1, 13, 15, 26, 6);  x0 += k1; x1 += k2 + 1u;
    tf4(x0, x1, 17, 29, 16, 24); x0 += k2; x1 += k0 + 2u;
    tf4(x0, x1, 13, 15, 26, 6);  x0 += k0; x1 += k1 + 3u;
    tf4(x0, x1, 17, 29, 16, 24); x0 += k1; x1 += k2 + 4u;
    tf4(x0, x1, 13, 15, 26, 6);  x0 += k2; x1 += k0 + 5u;
    o0 = x0; o1 = x1;
}
__global__ __launch_bounds__(256) void sample_k() {
    int n = blockIdx.x * 256 + threadIdx.x;
    float best = -__int_as_float(0x7f800000); int bj = 0;
    #pragma unroll
    for (int j = 0; j < 10; ++j) {
        unsigned m = (unsigned)n * 10u + (unsigned)j, o0, o1;
        threefry(0u, m, o0, o1);
        unsigned bits = o0 ^ o1;
        float f = __uint_as_float((bits >> 9) | 0x3f800000u) - 1.0f;
        float u = fmaxf(1e-10f, __fadd_rn(f, 1e-10f));
        float gum = -logf(-logf(u));
        float val = __fadd_rn(g_topd[n * 10 + j], gum);
        if (val > best) { best = val; bj = j; }
    }
    g_enc[n] = g_topi[n * 10 + bj];
}

// ------------- quantize (+fused fp16 shadow of h) -------------
__global__ __launch_bounds__(256) void quant_k(const float* __restrict__ cb) {
    int n = blockIdx.x;
    long long idx = g_enc[n];
    #pragma unroll
    for (int i = 0; i < 3; ++i) {
        int d = threadIdx.x + i * 256;
        long long o = (long long)n * 768 + d;
        float z = g_ze[o];
        float q = cb[idx * 768 + d];
        float hv = __fadd_rn(z, __fsub_rn(q, z));
        g_h[o] = hv;
        g_hsp[o] = __float2half(hv);
    }
}

// ------------- warp-per-row softmax: fp32 scores -> fp16 probs -------------
__global__ __launch_bounds__(256) void softmax_k() {
    long long r = (long long)blockIdx.x * 8 + (threadIdx.x >> 5);
    const int lane = threadIdx.x & 31;
    const float* row = g_scores + r * 512;
    float v[16];
    float m = -__int_as_float(0x7f800000);
    #pragma unroll
    for (int j = 0; j < 16; ++j) { v[j] = row[j * 32 + lane]; m = fmaxf(m, v[j]); }
    #pragma unroll
    for (int o = 16; o; o >>= 1) m = fmaxf(m, __shfl_xor_sync(0xffffffffu, m, o));
    float s = 0.f;
    #pragma unroll
    for (int j = 0; j < 16; ++j) { v[j] = __expf(v[j] - m); s += v[j]; }
    #pragma unroll
    for (int o = 16; o; o >>= 1) s += __shfl_xor_sync(0xffffffffu, s, o);
    #pragma unroll
    for (int j = 0; j < 16; ++j) {
        float p = __fdiv_rn(v[j], s);
        g_psp[r * 512 + j * 32 + lane] = __float2half(p);
    }
}

// ------------- residual + LayerNorm (+fused fp16 shadow of h) -------------
__global__ __launch_bounds__(256) void addln_k(float* __restrict__ h, const float* __restrict__ res,
                                               const float* __restrict__ g, const float* __restrict__ b) {
    int n = blockIdx.x;
    __shared__ float red[8];
    float v[3]; float s = 0.f;
    #pragma unroll
    for (int i = 0; i < 3; ++i) {
        int d = threadIdx.x + i * 256;
        v[i] = h[(long long)n * 768 + d] + res[(long long)n * 768 + d];
        s += v[i];
    }
    s = blkSum(s, red);
    float mean = s * (1.0f / 768.0f);
    float vs = 0.f;
    #pragma unroll
    for (int i = 0; i < 3; ++i) { float d0 = v[i] - mean; vs += d0 * d0; }
    vs = blkSum(vs, red);
    float inv = __fdiv_rn(1.0f, sqrtf(vs * (1.0f / 768.0f) + 1e-5f));
    #pragma unroll
    for (int i = 0; i < 3; ++i) {
        int d = threadIdx.x + i * 256;
        long long o = (long long)n * 768 + d;
        float hv = (v[i] - mean) * inv * g[d] + b[d];
        h[o] = hv;
        g_hsp[o] = __float2half(hv);
    }
}

// ------------- host side -------------
struct HArgs {
    int M, N, K;
    const __half *A; int lda; long long sA1, sA2;
    const __half *B; int ldb; long long Bs, sB1, sB2;
    float* Cf; __half* Cb; int ldc; long long sC1, sC2;
    cfp bias; float alpha; int Z, bdiv, Nreal;
    __half* Vt; int vbase; int causal;
};
static void hgemm(int npb, int epi, const HArgs& a) {
    dim3 g(a.N / 128, a.M / 128, a.Z);
    size_t sm = (size_t)(2 + 2 * npb) * TILEB;
    int ch = (a.K % 48 == 0) ? 3 : 2;
#define HG(NPV,EV,CV) hgemm_k<NPV,EV,CV><<<g,256,sm>>>(a.M,a.N,a.K,a.A,a.lda,a.sA1,a.sA2, \
    a.B,a.ldb,a.Bs,a.sB1,a.sB2,a.Cf,a.Cb,a.ldc,a.sC1,a.sC2,a.bias,a.alpha,a.bdiv,a.Nreal,a.Vt,a.vbase,a.causal)
    if (npb == 1) {
        if (epi == 10) HG(1,10,3);
        else if (epi == 8) HG(1,8,3);
        else HG(1,9,3);
        return;
    }
    if (ch == 3) {
        switch (epi) {
            case 1: HG(2,1,3); break;  case 2: HG(2,2,3); break;
            case 5: HG(2,5,3); break;  case 7: HG(2,7,3); break;
            default: HG(2,1,3); break;
        }
    } else {
        switch (epi) {
            case 6: HG(2,6,2); break;
            default: HG(2,1,2); break;
        }
    }
#undef HG
}
static void splitw(cfp x, __half* p, long long n, long long stride) {
    splitw_k<<<(unsigned)((n + 255) / 256), 256>>>(x, p, n, stride);
}

extern "C" void kernel_launch(void* const* d_in, const int* in_sizes, int n_in,
                              void* d_out, int out_size) {
    cfp x     = (cfp)d_in[0];
    cfp cb    = (cfp)d_in[1];
    cfp sa_in_w = (cfp)d_in[2],  sa_in_b = (cfp)d_in[3];
    cfp sa_out_w= (cfp)d_in[4],  sa_out_b= (cfp)d_in[5];
    cfp ca_in_w = (cfp)d_in[6],  ca_in_b = (cfp)d_in[7];
    cfp ca_out_w= (cfp)d_in[8],  ca_out_b= (cfp)d_in[9];
    cfp ln1_g = (cfp)d_in[10], ln1_b = (cfp)d_in[11];
    cfp ln2_g = (cfp)d_in[12], ln2_b = (cfp)d_in[13];
    cfp ln3_g = (cfp)d_in[14], ln3_b = (cfp)d_in[15];
    cfp ff_w1 = (cfp)d_in[16], ff_b1 = (cfp)d_in[17];
    cfp ff_w2 = (cfp)d_in[18], ff_b2 = (cfp)d_in[19];
    cfp out_w = (cfp)d_in[20], out_b = (cfp)d_in[21];
    float* out = (float*)d_out;

    cudaFuncSetAttribute(hgemm_k<1,10,3>, cudaFuncAttributeMaxDynamicSharedMemorySize, 4 * TILEB);
    cudaFuncSetAttribute(hgemm_k<1,8,3>,  cudaFuncAttributeMaxDynamicSharedMemorySize, 4 * TILEB);
    cudaFuncSetAttribute(hgemm_k<1,9,3>,  cudaFuncAttributeMaxDynamicSharedMemorySize, 4 * TILEB);
    cudaFuncSetAttribute(hgemm_k<2,1,3>,  cudaFuncAttributeMaxDynamicSharedMemorySize, 6 * TILEB);
    cudaFuncSetAttribute(hgemm_k<2,2,3>,  cudaFuncAttributeMaxDynamicSharedMemorySize, 6 * TILEB);
    cudaFuncSetAttribute(hgemm_k<2,5,3>,  cudaFuncAttributeMaxDynamicSharedMemorySize, 6 * TILEB);
    cudaFuncSetAttribute(hgemm_k<2,7,3>,  cudaFuncAttributeMaxDynamicSharedMemorySize, 6 * TILEB);
    cudaFuncSetAttribute(hgemm_k<2,1,2>,  cudaFuncAttributeMaxDynamicSharedMemorySize, 6 * TILEB);
    cudaFuncSetAttribute(hgemm_k<2,6,2>,  cudaFuncAttributeMaxDynamicSharedMemorySize, 6 * TILEB);

    float *ze, *h, *proj, *scores, *padb;
    __half *dotb, *zsp, *hsp, *atsp, *fsp, *qsp, *cbsp, *psp, *vtsp, *wall;
    cudaGetSymbolAddress((void**)&ze, g_ze);
    cudaGetSymbolAddress((void**)&h, g_h);
    cudaGetSymbolAddress((void**)&proj, g_proj);
    cudaGetSymbolAddress((void**)&scores, g_scores);
    cudaGetSymbolAddress((void**)&padb, g_padbias);
    cudaGetSymbolAddress((void**)&dotb, g_dotb);
    cudaGetSymbolAddress((void**)&zsp, g_zsp);
    cudaGetSymbolAddress((void**)&hsp, g_hsp);
    cudaGetSymbolAddress((void**)&atsp, g_atsp);
    cudaGetSymbolAddress((void**)&fsp, g_fsp);
    cudaGetSymbolAddress((void**)&qsp, g_qsp);
    cudaGetSymbolAddress((void**)&cbsp, g_cbsp);
    cudaGetSymbolAddress((void**)&psp, g_psp);
    cudaGetSymbolAddress((void**)&vtsp, g_vtsp);
    cudaGetSymbolAddress((void**)&wall, g_wall);

    const float sc = sqrtf(96.f);

    // ---- pre-split ALL weights into the wall (fp16 split-2, plane stride NW) ----
    splitw(sa_in_w,  wall + W_SIW, 10616832LL, NW);
    splitw(sa_out_w, wall + W_SOW, 3538944LL,  NW);
    splitw(ca_in_w,  wall + W_CIW, 10616832LL, NW);
    splitw(ca_out_w, wall + W_COW, 3538944LL,  NW);
    splitw(ff_w1,    wall + W_W1,  9437184LL,  NW);
    splitw(ff_w2,    wall + W_W2,  9437184LL,  NW);
    splitw(out_w,    wall + W_OW,  589824LL,   NW);

    // ---- VQ: coarse fp16 dots -> exact rerank ----
    ze_kernel<<<8192, 256>>>(x);
    cn_kernel<<<8192, 256>>>(cb);
    tohalf_k<<<(unsigned)((NA + 255) / 256), 256>>>(cb, cbsp, NA);
    { HArgs a = {8192, 8192, 768, zsp, 768, 0, 0, cbsp, 768, 0, 0, 0,
                 nullptr, dotb, 8192, 0, 0, nullptr, 1.f, 1, 1, 0, nullptr, 0, 0};
      hgemm(1, 10, a); }
    topk16_k<<<8192, 256>>>();
    rerank_k<<<8192, 256>>>(cb);
    sample_k<<<32, 256>>>();
    quant_k<<<8192, 256>>>(cb);

    for (int l = 0; l < 6; ++l) {
        const __half* siw = wall + W_SIW + (long long)l * 2304 * 768;
        const __half* sow = wall + W_SOW + (long long)l * 768 * 768;
        const __half* ciw = wall + W_CIW + (long long)l * 2304 * 768;
        const __half* cow = wall + W_COW + (long long)l * 768 * 768;
        const __half* w1  = wall + W_W1  + (long long)l * 2048 * 768;
        const __half* w2  = wall + W_W2  + (long long)l * 768 * 2048;
        cfp sib = sa_in_b + l * 2304, sob = sa_out_b + l * 768;
        cfp cib = ca_in_b + l * 2304, cob = ca_out_b + l * 768;
        cfp b1 = ff_b1 + l * 2048, b2 = ff_b2 + l * 768;

        for (int att = 0; att < 2; ++att) {
            // qkv projections -> qsp (+ V transposed split-2 into vtsp)
            if (att == 0) {
                HArgs a = {8192, 2304, 768, hsp, 768, 0, 0, siw, 768, NW, 0, 0,
                           nullptr, qsp, 2304, 0, 0, sib, 0.f, 1, 1, 0, vtsp, 1536, 0};
                hgemm(2, 7, a);
            } else {
                HArgs aq = {8192, 768, 768, hsp, 768, 0, 0, ciw, 768, NW, 0, 0,
                            nullptr, qsp, 2304, 0, 0, cib, 0.f, 1, 1, 0, nullptr, 0, 0};
                hgemm(2, 5, aq);
                HArgs akv = {8192, 1536, 768, zsp, 768, 0, 0, ciw + 768LL * 768, 768, NW, 0, 0,
                             nullptr, qsp + 768, 2304, 0, 0, cib + 768, 0.f, 1, 1, 0, vtsp, 768, 0};
                hgemm(2, 7, akv);
            }
            // scores = q@k^T / sc + mask  (both single-plane fp16; EPI8 skips masked tiles)
            { HArgs a = {512, 512, 96, qsp, 2304, 512LL * 2304, 96,
                         qsp + 768, 2304, 0, 512LL * 2304, 96,
                         scores, nullptr, 512, 8LL * 262144, 262144,
                         padb, sc, 128, 8, 0, nullptr, 0, 0};
              hgemm(1, att == 0 ? 8 : 9, a); }
            softmax_k<<<8192, 256>>>();
            // attn = probs @ v  (A=probs single, B=vT split-2; self skips zero chunks)
            { HArgs a = {512, 128, 512, psp, 512, 8LL * 262144, 262144,
                         vtsp, 512, NVT, 8LL * 65536, 65536,
                         nullptr, atsp, 768, 512LL * 768, 96,
                         nullptr, 1.f, 128, 8, 96, nullptr, 0, att == 0 ? 1 : 0};
              hgemm(2, 6, a); }
            // out projection + addln
            { HArgs a = {8192, 768, 768, atsp, 768, 0, 0, att == 0 ? sow : cow, 768, NW, 0, 0,
                         proj, nullptr, 768, 0, 0, att == 0 ? sob : cob, 0.f, 1, 1, 0, nullptr, 0, 0};
              hgemm(2, 1, a); }
            addln_k<<<8192, 256>>>(h, proj,
                (att == 0 ? ln1_g : ln2_g) + l * 768, (att == 0 ? ln1_b : ln2_b) + l * 768);
        }

        // ---- feed-forward ----
        { HArgs a = {8192, 2048, 768, hsp, 768, 0, 0, w1, 768, NW, 0, 0,
                     nullptr, fsp, 2048, 0, 0, b1, 0.f, 1, 1, 0, nullptr, 0, 0};
          hgemm(2, 2, a); }
        { HArgs a = {8192, 768, 2048, fsp, 2048, 0, 0, w2, 2048, NW, 0, 0,
                     proj, nullptr, 768, 0, 0, b2, 0.f, 1, 1, 0, nullptr, 0, 0};
          hgemm(2, 1, a); }
        addln_k<<<8192, 256>>>(h, proj, ln3_g + l * 768, ln3_b + l * 768);
    }

    // ---- output projection ----
    { HArgs a = {8192, 768, 768, hsp, 768, 0, 0, wall + W_OW, 768, NW, 0, 0,
                 out, nullptr, 768, 0, 0, out_b, 0.f, 1, 1, 0, nullptr, 0, 0};
      hgemm(2, 1, a); }
}